// round 7
// baseline (speedup 1.0000x reference)
#include <cuda_runtime.h>
#include <cuda_bf16.h>
#include <math.h>
#include <stdint.h>

// ---------------- problem constants ----------------
static constexpr int NTOK = 2048;
static constexpr int Dm   = 1024;
static constexpr int NEXP = 12;
static constexpr int HSh  = 2048;   // shared hidden
static constexpr int HRt  = 3072;   // routed hidden
static constexpr float TAU = 1.5f;

// ---------------- device scratch ----------------
__device__ int   g_cnt[NEXP];
__device__ int   g_off[NEXP];
__device__ int   g_bucket[NEXP * NTOK];
__device__ float g_bw[NEXP * NTOK];

__device__ __nv_bfloat16 g_xh[(size_t)NTOK * Dm],  g_xl[(size_t)NTOK * Dm];
__device__ __nv_bfloat16 g_ash[(size_t)NTOK * HSh], g_asl[(size_t)NTOK * HSh];
__device__ __nv_bfloat16 g_arh[(size_t)2 * NTOK * HRt], g_arl[(size_t)2 * NTOK * HRt];

// ---------------- helpers ----------------
__device__ __forceinline__ uint32_t smem_u32(const void* p) {
    uint32_t a;
    asm("{ .reg .u64 t; cvta.to.shared.u64 t, %1; cvt.u32.u64 %0, t; }" : "=r"(a) : "l"(p));
    return a;
}
__device__ __forceinline__ uint32_t swzA(uint32_t b) { return b ^ ((b >> 3) & 0x70); }
// B tile: [K=64 rows, 128 bf16 cols], 256B rows, 16B-granule xor swizzle
__device__ __forceinline__ uint32_t bofs(int k, int nb /*byte in row, 16B aligned*/) {
    return (uint32_t)(k * 256 + (((nb >> 4) ^ (k & 7)) << 4) + (nb & 15));
}

__device__ __forceinline__ void cp16(uint32_t dst, const void* src, int sz) {
    asm volatile("cp.async.cg.shared.global [%0], [%1], 16, %2;"
                 :: "r"(dst), "l"(src), "r"(sz));
}
#define CP_COMMIT() asm volatile("cp.async.commit_group;" ::: "memory")

__device__ __forceinline__ void ldsm4(uint32_t* r, uint32_t addr) {
    asm volatile("ldmatrix.sync.aligned.m8n8.x4.shared.b16 {%0,%1,%2,%3}, [%4];"
                 : "=r"(r[0]), "=r"(r[1]), "=r"(r[2]), "=r"(r[3]) : "r"(addr));
}
__device__ __forceinline__ void ldsm4t(uint32_t* r, uint32_t addr) {
    asm volatile("ldmatrix.sync.aligned.m8n8.x4.trans.shared.b16 {%0,%1,%2,%3}, [%4];"
                 : "=r"(r[0]), "=r"(r[1]), "=r"(r[2]), "=r"(r[3]) : "r"(addr));
}
__device__ __forceinline__ void mma16816(float* c, const uint32_t* a, const uint32_t* b) {
    asm volatile(
        "mma.sync.aligned.m16n8k16.row.col.f32.bf16.bf16.f32 "
        "{%0,%1,%2,%3}, {%4,%5,%6,%7}, {%8,%9}, {%0,%1,%2,%3};"
        : "+f"(c[0]), "+f"(c[1]), "+f"(c[2]), "+f"(c[3])
        : "r"(a[0]), "r"(a[1]), "r"(a[2]), "r"(a[3]), "r"(b[0]), "r"(b[1]));
}
__device__ __forceinline__ void split_bf16(float v, __nv_bfloat16& h, __nv_bfloat16& l) {
    h = __float2bfloat16(v);
    l = __float2bfloat16(v - __bfloat162float(h));
}
__device__ __forceinline__ uint32_t pack2(__nv_bfloat16 a, __nv_bfloat16 b) {
    return (uint32_t)__bfloat16_as_ushort(a) | ((uint32_t)__bfloat16_as_ushort(b) << 16);
}
__device__ __forceinline__ float gelu_exact(float g) {
    return 0.5f * g * (1.0f + erff(g * 0.70710678118654752f));
}

// ---------------- tiny kernels ----------------
__global__ void prefix_k() {
    if (threadIdx.x == 0) {
        int s = 0;
        for (int e = 0; e < NEXP; e++) { g_off[e] = s; s += g_cnt[e]; }
    }
}

__global__ void router_k(const float* __restrict__ x,
                         const float* __restrict__ Wr,
                         const float* __restrict__ br) {
    int n = blockIdx.x, tid = threadIdx.x;            // 128 threads
    __shared__ float red[128 * NEXP];
    __shared__ float lg[NEXP];
    float part[NEXP];
#pragma unroll
    for (int e = 0; e < NEXP; e++) part[e] = 0.f;
    const float* xr = x + (size_t)n * Dm;
    for (int d = tid; d < Dm; d += 128) {
        float xv = xr[d];
        const float* wr = Wr + (size_t)d * NEXP;
#pragma unroll
        for (int e = 0; e < NEXP; e++) part[e] += xv * wr[e];
    }
#pragma unroll
    for (int e = 0; e < NEXP; e++) red[tid * NEXP + e] = part[e];
    __syncthreads();
    if (tid < NEXP) {
        float s = 0.f;
        for (int i = 0; i < 128; i++) s += red[i * NEXP + tid];
        lg[tid] = (s + br[tid]) / TAU;
    }
    __syncthreads();
    if (tid == 0) {
        int i0 = 0; float v0 = lg[0];
#pragma unroll
        for (int e = 1; e < NEXP; e++) if (lg[e] > v0) { v0 = lg[e]; i0 = e; }
        int i1 = -1; float v1 = -3.4e38f;
#pragma unroll
        for (int e = 0; e < NEXP; e++) if (e != i0 && lg[e] > v1) { v1 = lg[e]; i1 = e; }
        float e1 = __expf(v1 - v0);
        float inv = 1.f / (1.f + e1);
        int s0 = atomicAdd(&g_cnt[i0], 1);
        g_bucket[i0 * NTOK + s0] = n;  g_bw[i0 * NTOK + s0] = inv;
        int s1 = atomicAdd(&g_cnt[i1], 1);
        g_bucket[i1 * NTOK + s1] = n;  g_bw[i1 * NTOK + s1] = e1 * inv;
    }
}

// vectorized split fp32 -> bf16 hi/lo; block 0 also zeros expert counters
__global__ void split_k(const float4* __restrict__ s, uint2* __restrict__ dh,
                        uint2* __restrict__ dl, int n4) {
    if (blockIdx.x == 0 && threadIdx.x < NEXP) g_cnt[threadIdx.x] = 0;
    int i = blockIdx.x * 256 + threadIdx.x;
    if (i >= n4) return;
    float4 v = s[i];
    __nv_bfloat16 h[4], l[4];
    split_bf16(v.x, h[0], l[0]); split_bf16(v.y, h[1], l[1]);
    split_bf16(v.z, h[2], l[2]); split_bf16(v.w, h[3], l[3]);
    dh[i] = make_uint2(pack2(h[0], h[1]), pack2(h[2], h[3]));
    dl[i] = make_uint2(pack2(l[0], l[1]), pack2(l[2], l[3]));
}

// ---------------- fused HMMA GEMM (weights converted in-kernel) ----------------
// A: bf16 hi/lo [M, K] row-major. B: ORIGINAL fp32 weights [K, Nsrc] k-major.
// CTA tile: 128 M x 128 B-cols. Warp tile 16 M x 128 N (8 warps).
// GEGLU: B cols taken from {a: bx*64+c, g: Hout+bx*64+c}, interleaved n'=2c/2c+1;
//        epilogue writes bf16 hi/lo activations a*gelu(g), width Hout=Nsrc/2.
// MODE 0: plain rows. MODE 1: A rows gathered via bucket (expert=blockIdx.z),
//         out row off[e]+m. MODE 2: A rows off[e]+m, atomicAdd(C[token], w*(acc+bias)).
static constexpr int AT_B   = 16384;          // one A tile (128 x 128B)
static constexpr int SG_B   = 32768;          // fp32 staging (64 x 512B)
static constexpr int OFF_SG = 2 * 2 * AT_B;   // 65536
static constexpr int OFF_BB = OFF_SG + 2 * SG_B;  // 131072
static constexpr int GSMEM  = OFF_BB + 2 * AT_B;  // 163840

template <int MODE, bool GEGLU>
__global__ void __launch_bounds__(256, 1)
fgemm(const __nv_bfloat16* __restrict__ Ah, const __nv_bfloat16* __restrict__ Al,
      const float* __restrict__ B, const float* __restrict__ bias,
      float* __restrict__ C, __nv_bfloat16* __restrict__ OH,
      __nv_bfloat16* __restrict__ OL, int M, int Nsrc, int K) {
    extern __shared__ char sm[];
    __shared__ int   sb_tok[128];
    __shared__ float sb_w[128];

    const int tid = threadIdx.x, wid = tid >> 5, lane = tid & 31;
    const int row0 = blockIdx.y * 128;
    const int Hout = Nsrc >> 1;

    int e = 0, Me = M, offE = 0;
    if constexpr (MODE != 0) {
        e = blockIdx.z;
        Me = g_cnt[e];
        if (row0 >= Me) return;
        offE = g_off[e];
        B    += (size_t)e * K * Nsrc;
        bias += (size_t)e * Nsrc;
    }
    if constexpr (MODE != 0) {
        if (tid < 128) {
            int r = row0 + tid;
            sb_tok[tid] = (r < Me) ? g_bucket[e * NTOK + r] : 0;
            sb_w[tid]   = (r < Me) ? g_bw[e * NTOK + r] : 0.f;
        }
        __syncthreads();
    }

    const int nch = K >> 6;
    const uint32_t smb = smem_u32(sm);
    const uint32_t bbh = smb + OFF_BB, bbl = bbh + AT_B;
    // src col bases
    const int colA0 = GEGLU ? blockIdx.x * 64 : blockIdx.x * 128;

    auto issue_chunk = [&](int ck) {
        const int buf = ck & 1, k0 = ck << 6;
        const uint32_t abase = smb + buf * 2 * AT_B;
        const uint32_t sgbase = smb + OFF_SG + buf * SG_B;
        // A tiles: 2048 slots of 16B
#pragma unroll
        for (int s = tid; s < 2048; s += 256) {
            int t = s >> 10, slot = s & 1023;
            int r = slot >> 3, cc = slot & 7;
            uint32_t dst = abase + t * AT_B + swzA((uint32_t)(r * 128 + cc * 16));
            const __nv_bfloat16* Ab = (t == 0) ? Ah : Al;
            size_t ro = 0; int sz = 16;
            if constexpr (MODE == 1) {
                if (row0 + r < Me) ro = (size_t)sb_tok[r] * K; else sz = 0;
            } else if constexpr (MODE == 2) {
                if (row0 + r < Me) ro = (size_t)(offE + row0 + r) * K; else sz = 0;
            } else {
                ro = (size_t)(row0 + r) * K;
            }
            cp16(dst, Ab + ro + k0 + cc * 8, sz);
        }
        // B fp32 staging: 2048 slots of 16B; layout [64][128] fp32
#pragma unroll
        for (int s = tid; s < 2048; s += 256) {
            int k = s >> 5, jg = s & 31;
            int j0 = jg * 4;
            uint32_t dst = sgbase + (uint32_t)(k * 512 + j0 * 4);
            int srccol;
            if constexpr (GEGLU) srccol = (j0 < 64) ? (colA0 + j0) : (Hout + colA0 + j0 - 64);
            else                 srccol = colA0 + j0;
            cp16(dst, B + (size_t)(k0 + k) * Nsrc + srccol, 16);
        }
        CP_COMMIT();
    };

    float acc[16][4];
#pragma unroll
    for (int j = 0; j < 16; j++)
#pragma unroll
        for (int k = 0; k < 4; k++) acc[j][k] = 0.f;

    issue_chunk(0);
    for (int ck = 0; ck < nch; ck++) {
        asm volatile("cp.async.wait_group 0;" ::: "memory");
        __syncthreads();
        if (ck + 1 < nch) issue_chunk(ck + 1);

        // convert staging fp32 -> Bh/Bl bf16 (interleaved for GEGLU)
        {
            const uint32_t sgbase = smb + OFF_SG + (ck & 1) * SG_B;
            const char* sg = sm + (sgbase - smb);
#pragma unroll
            for (int t = 0; t < 8; t++) {
                int k = wid * 8 + t;
                uint32_t wb = bbh + bofs(k, lane * 8);
                uint32_t wl = bbl + bofs(k, lane * 8);
                if constexpr (GEGLU) {
                    float2 av = *(const float2*)(sg + k * 512 + lane * 8);
                    float2 gv = *(const float2*)(sg + k * 512 + 256 + lane * 8);
                    __nv_bfloat16 h0, l0, h1, l1, h2, l2, h3, l3;
                    split_bf16(av.x, h0, l0); split_bf16(gv.x, h1, l1);
                    split_bf16(av.y, h2, l2); split_bf16(gv.y, h3, l3);
                    *(uint2*)(sm + (wb - smb)) = make_uint2(pack2(h0, h1), pack2(h2, h3));
                    *(uint2*)(sm + (wl - smb)) = make_uint2(pack2(l0, l1), pack2(l2, l3));
                } else {
                    float4 v = *(const float4*)(sg + k * 512 + lane * 16);
                    __nv_bfloat16 h0, l0, h1, l1, h2, l2, h3, l3;
                    split_bf16(v.x, h0, l0); split_bf16(v.y, h1, l1);
                    split_bf16(v.z, h2, l2); split_bf16(v.w, h3, l3);
                    *(uint2*)(sm + (wb - smb)) = make_uint2(pack2(h0, h1), pack2(h2, h3));
                    *(uint2*)(sm + (wl - smb)) = make_uint2(pack2(l0, l1), pack2(l2, l3));
                }
            }
        }
        __syncthreads();

        const uint32_t abase = smb + (ck & 1) * 2 * AT_B;
#pragma unroll
        for (int ks = 0; ks < 4; ks++) {
            uint32_t ah[4], al[4];
            {
                int rrow = wid * 16 + (lane & 15);
                uint32_t byte = swzA((uint32_t)(rrow * 128 + ks * 32 + (lane >> 4) * 16));
                ldsm4(ah, abase + byte);
                ldsm4(al, abase + AT_B + byte);
            }
            const int sub = lane >> 3, i8 = lane & 7;
            const int kk = ks * 16 + (sub & 1) * 8 + i8;
#pragma unroll
            for (int g = 0; g < 8; g++) {
                int nn = g * 16 + (sub >> 1) * 8;
                uint32_t byte = bofs(kk, nn * 2);
                uint32_t bh[4], bl[4];
                ldsm4t(bh, bbh + byte);
                ldsm4t(bl, bbl + byte);
                mma16816(acc[2 * g],     ah, bh);
                mma16816(acc[2 * g],     ah, bl);
                mma16816(acc[2 * g],     al, bh);
                mma16816(acc[2 * g + 1], ah, bh + 2);
                mma16816(acc[2 * g + 1], ah, bl + 2);
                mma16816(acc[2 * g + 1], al, bh + 2);
            }
        }
        __syncthreads();
    }

    // ---------------- epilogue ----------------
#pragma unroll
    for (int half = 0; half < 2; half++) {
        int ml = wid * 16 + (lane >> 2) + half * 8;
        if constexpr (MODE != 0) { if (row0 + ml >= Me) continue; }
#pragma unroll
        for (int nf = 0; nf < 16; nf++) {
            int cp = (lane & 3) * 2;
            if constexpr (GEGLU) {
                int cglob = colA0 + nf * 4 + (cp >> 1);
                float a = acc[nf][half * 2 + 0] + __ldg(bias + cglob);
                float g = acc[nf][half * 2 + 1] + __ldg(bias + Hout + cglob);
                float v = a * gelu_exact(g);
                __nv_bfloat16 vh, vl; split_bf16(v, vh, vl);
                size_t rr = (MODE != 0) ? (size_t)(offE + row0 + ml) : (size_t)(row0 + ml);
                OH[rr * Hout + cglob] = vh;
                OL[rr * Hout + cglob] = vl;
            } else {
                int colb = colA0 + nf * 8 + cp;
                float v0 = acc[nf][half * 2 + 0] + __ldg(bias + colb + 0);
                float v1 = acc[nf][half * 2 + 1] + __ldg(bias + colb + 1);
                if constexpr (MODE == 2) {
                    int tok = sb_tok[ml];
                    float w = sb_w[ml];
                    float* op = C + (size_t)tok * Nsrc + colb;
                    atomicAdd(op + 0, w * v0);
                    atomicAdd(op + 1, w * v1);
                } else {
                    float2* cpp = (float2*)(C + (size_t)(row0 + ml) * Nsrc + colb);
                    *cpp = make_float2(v0, v1);
                }
            }
        }
    }
}

// ---------------- launch ----------------
extern "C" void kernel_launch(void* const* d_in, const int* in_sizes, int n_in,
                              void* d_out, int out_size) {
    const float* x   = (const float*)d_in[0];
    const float* Ws1 = (const float*)d_in[1];
    const float* bs1 = (const float*)d_in[2];
    const float* Ws2 = (const float*)d_in[3];
    const float* bs2 = (const float*)d_in[4];
    const float* We1 = (const float*)d_in[5];
    const float* be1 = (const float*)d_in[6];
    const float* We2 = (const float*)d_in[7];
    const float* be2 = (const float*)d_in[8];
    const float* Wr  = (const float*)d_in[9];
    const float* br  = (const float*)d_in[10];
    float* out = (float*)d_out;

    cudaFuncSetAttribute(fgemm<0, true>,  cudaFuncAttributeMaxDynamicSharedMemorySize, GSMEM);
    cudaFuncSetAttribute(fgemm<0, false>, cudaFuncAttributeMaxDynamicSharedMemorySize, GSMEM);
    cudaFuncSetAttribute(fgemm<1, true>,  cudaFuncAttributeMaxDynamicSharedMemorySize, GSMEM);
    cudaFuncSetAttribute(fgemm<2, false>, cudaFuncAttributeMaxDynamicSharedMemorySize, GSMEM);

    __nv_bfloat16 *p_xh, *p_xl, *p_ash, *p_asl, *p_arh, *p_arl;
    cudaGetSymbolAddress((void**)&p_xh, g_xh);   cudaGetSymbolAddress((void**)&p_xl, g_xl);
    cudaGetSymbolAddress((void**)&p_ash, g_ash); cudaGetSymbolAddress((void**)&p_asl, g_asl);
    cudaGetSymbolAddress((void**)&p_arh, g_arh); cudaGetSymbolAddress((void**)&p_arl, g_arl);

    // 0: split x (also zeros expert counters)
    split_k<<<(NTOK * Dm / 4 + 255) / 256, 256>>>(
        (const float4*)x, (uint2*)p_xh, (uint2*)p_xl, NTOK * Dm / 4);
    // 1-2: routing
    router_k<<<NTOK, 128>>>(x, Wr, br);
    prefix_k<<<1, 1>>>();
    // 3 (profiled): routed GEMM1 + GEGLU  -> g_ar (bf16 hi/lo)
    fgemm<1, true><<<dim3(HRt / 64, NTOK / 128, NEXP), 256, GSMEM>>>(
        p_xh, p_xl, We1, be1, nullptr, p_arh, p_arl, 0, 2 * HRt, Dm);
    // 4: shared GEMM1 + GEGLU -> g_as
    fgemm<0, true><<<dim3(HSh / 64, NTOK / 128), 256, GSMEM>>>(
        p_xh, p_xl, Ws1, bs1, nullptr, p_ash, p_asl, NTOK, 2 * HSh, Dm);
    // 5: shared GEMM2 -> out (full overwrite)
    fgemm<0, false><<<dim3(Dm / 128, NTOK / 128), 256, GSMEM>>>(
        p_ash, p_asl, Ws2, bs2, out, nullptr, nullptr, NTOK, Dm, HSh);
    // 6: routed GEMM2 -> atomic scatter into out
    fgemm<2, false><<<dim3(Dm / 128, NTOK / 128, NEXP), 256, GSMEM>>>(
        p_arh, p_arl, We2, be2, out, nullptr, nullptr, 0, Dm, HRt);
}

// round 8
// speedup vs baseline: 1.6796x; 1.6796x over previous
#include <cuda_runtime.h>
#include <cuda_bf16.h>
#include <math.h>
#include <stdint.h>

// ---------------- problem constants ----------------
static constexpr int NTOK = 2048;
static constexpr int Dm   = 1024;
static constexpr int NEXP = 12;
static constexpr int HSh  = 2048;   // shared hidden
static constexpr int HRt  = 3072;   // routed hidden
static constexpr float TAU = 1.5f;

// ---------------- device scratch ----------------
__device__ int   g_cnt[NEXP];
__device__ int   g_off[NEXP];
__device__ int   g_bucket[NEXP * NTOK];
__device__ float g_bw[NEXP * NTOK];

__device__ __nv_bfloat16 g_xh[(size_t)NTOK * Dm],  g_xl[(size_t)NTOK * Dm];
__device__ __nv_bfloat16 g_ash[(size_t)NTOK * HSh], g_asl[(size_t)NTOK * HSh];
__device__ __nv_bfloat16 g_arh[(size_t)2 * NTOK * HRt], g_arl[(size_t)2 * NTOK * HRt];
// converted weights, SAME [K, N] layout as source (W1: a/g column-interleaved)
__device__ __nv_bfloat16 g_w1h[(size_t)Dm * 2 * HSh], g_w1l[(size_t)Dm * 2 * HSh];
__device__ __nv_bfloat16 g_w2h[(size_t)HSh * Dm],     g_w2l[(size_t)HSh * Dm];
__device__ __nv_bfloat16 g_e1h[(size_t)NEXP * Dm * 2 * HRt], g_e1l[(size_t)NEXP * Dm * 2 * HRt];
__device__ __nv_bfloat16 g_e2h[(size_t)NEXP * HRt * Dm],     g_e2l[(size_t)NEXP * HRt * Dm];

// ---------------- helpers ----------------
__device__ __forceinline__ uint32_t smem_u32(const void* p) {
    uint32_t a;
    asm("{ .reg .u64 t; cvta.to.shared.u64 t, %1; cvt.u32.u64 %0, t; }" : "=r"(a) : "l"(p));
    return a;
}
__device__ __forceinline__ uint32_t swzA(uint32_t b) { return b ^ ((b >> 3) & 0x70); }
// B tile: [64 k-rows][128 n-cols bf16] = 256B rows; 16B-granule xor swizzle (R7-validated)
__device__ __forceinline__ uint32_t bofs(int k, int nb) {
    return (uint32_t)(k * 256 + (((nb >> 4) ^ (k & 7)) << 4) + (nb & 15));
}

__device__ __forceinline__ void cp16(uint32_t dst, const void* src, int sz) {
    asm volatile("cp.async.cg.shared.global [%0], [%1], 16, %2;"
                 :: "r"(dst), "l"(src), "r"(sz));
}
#define CP_COMMIT() asm volatile("cp.async.commit_group;" ::: "memory")

__device__ __forceinline__ void ldsm4(uint32_t* r, uint32_t addr) {
    asm volatile("ldmatrix.sync.aligned.m8n8.x4.shared.b16 {%0,%1,%2,%3}, [%4];"
                 : "=r"(r[0]), "=r"(r[1]), "=r"(r[2]), "=r"(r[3]) : "r"(addr));
}
__device__ __forceinline__ void ldsm4t(uint32_t* r, uint32_t addr) {
    asm volatile("ldmatrix.sync.aligned.m8n8.x4.trans.shared.b16 {%0,%1,%2,%3}, [%4];"
                 : "=r"(r[0]), "=r"(r[1]), "=r"(r[2]), "=r"(r[3]) : "r"(addr));
}
__device__ __forceinline__ void mma16816(float* c, const uint32_t* a, const uint32_t* b) {
    asm volatile(
        "mma.sync.aligned.m16n8k16.row.col.f32.bf16.bf16.f32 "
        "{%0,%1,%2,%3}, {%4,%5,%6,%7}, {%8,%9}, {%0,%1,%2,%3};"
        : "+f"(c[0]), "+f"(c[1]), "+f"(c[2]), "+f"(c[3])
        : "r"(a[0]), "r"(a[1]), "r"(a[2]), "r"(a[3]), "r"(b[0]), "r"(b[1]));
}
__device__ __forceinline__ void split_bf16(float v, __nv_bfloat16& h, __nv_bfloat16& l) {
    h = __float2bfloat16(v);
    l = __float2bfloat16(v - __bfloat162float(h));
}
__device__ __forceinline__ uint32_t pack2(__nv_bfloat16 a, __nv_bfloat16 b) {
    return (uint32_t)__bfloat16_as_ushort(a) | ((uint32_t)__bfloat16_as_ushort(b) << 16);
}
__device__ __forceinline__ float gelu_exact(float g) {
    return 0.5f * g * (1.0f + erff(g * 0.70710678118654752f));
}

// ---------------- tiny kernels ----------------
__global__ void zero_k() { if (threadIdx.x < NEXP) g_cnt[threadIdx.x] = 0; }

__global__ void prefix_k() {
    if (threadIdx.x == 0) {
        int s = 0;
        for (int e = 0; e < NEXP; e++) { g_off[e] = s; s += g_cnt[e]; }
    }
}

__global__ void router_k(const float* __restrict__ x,
                         const float* __restrict__ Wr,
                         const float* __restrict__ br) {
    int n = blockIdx.x, tid = threadIdx.x;            // 128 threads
    __shared__ float red[128 * NEXP];
    __shared__ float lg[NEXP];
    float part[NEXP];
#pragma unroll
    for (int e = 0; e < NEXP; e++) part[e] = 0.f;
    const float* xr = x + (size_t)n * Dm;
    for (int d = tid; d < Dm; d += 128) {
        float xv = xr[d];
        const float* wr = Wr + (size_t)d * NEXP;
#pragma unroll
        for (int e = 0; e < NEXP; e++) part[e] += xv * wr[e];
    }
#pragma unroll
    for (int e = 0; e < NEXP; e++) red[tid * NEXP + e] = part[e];
    __syncthreads();
    if (tid < NEXP) {
        float s = 0.f;
        for (int i = 0; i < 128; i++) s += red[i * NEXP + tid];
        lg[tid] = (s + br[tid]) / TAU;
    }
    __syncthreads();
    if (tid == 0) {
        int i0 = 0; float v0 = lg[0];
#pragma unroll
        for (int e = 1; e < NEXP; e++) if (lg[e] > v0) { v0 = lg[e]; i0 = e; }
        int i1 = -1; float v1 = -3.4e38f;
#pragma unroll
        for (int e = 0; e < NEXP; e++) if (e != i0 && lg[e] > v1) { v1 = lg[e]; i1 = e; }
        float e1 = __expf(v1 - v0);
        float inv = 1.f / (1.f + e1);
        int s0 = atomicAdd(&g_cnt[i0], 1);
        g_bucket[i0 * NTOK + s0] = n;  g_bw[i0 * NTOK + s0] = inv;
        int s1 = atomicAdd(&g_cnt[i1], 1);
        g_bucket[i1 * NTOK + s1] = n;  g_bw[i1 * NTOK + s1] = e1 * inv;
    }
}

// vectorized split fp32 -> bf16 hi/lo (layout-preserving, n multiple of 4)
__global__ void split_k(const float4* __restrict__ s, uint2* __restrict__ dh,
                        uint2* __restrict__ dl, int n4) {
    int i = blockIdx.x * 256 + threadIdx.x;
    if (i >= n4) return;
    float4 v = s[i];
    __nv_bfloat16 h[4], l[4];
    split_bf16(v.x, h[0], l[0]); split_bf16(v.y, h[1], l[1]);
    split_bf16(v.z, h[2], l[2]); split_bf16(v.w, h[3], l[3]);
    dh[i] = make_uint2(pack2(h[0], h[1]), pack2(h[2], h[3]));
    dl[i] = make_uint2(pack2(l[0], l[1]), pack2(l[2], l[3]));
}

// W1 conversion: fp32 [K, 2H] -> bf16 hi/lo [K, 2H] with a/g column interleave
// (out col 2c <- src col c, out col 2c+1 <- src col H+c). blockIdx.y = expert.
__global__ void wsplit_ilv_k(const float* __restrict__ W, __nv_bfloat16* __restrict__ oh,
                             __nv_bfloat16* __restrict__ ol, int K, int H) {
    int i = blockIdx.x * 256 + threadIdx.x;
    if (i >= K * H) return;
    int k = i / H, c = i - k * H;
    size_t zo = (size_t)blockIdx.y * K * 2 * H;
    const float* wr = W + zo + (size_t)k * 2 * H;
    float a = wr[c], g = wr[H + c];
    __nv_bfloat16 ah, al, gh, gl;
    split_bf16(a, ah, al); split_bf16(g, gh, gl);
    size_t o = zo + (size_t)k * 2 * H + 2 * c;
    *(uint32_t*)(oh + o) = pack2(ah, gh);
    *(uint32_t*)(ol + o) = pack2(al, gl);
}

// ---------------- HMMA bf16x3 GEMM ----------------
// A: bf16 hi/lo [M, K] row-major (swzA tiles, ldsm4).
// B: bf16 hi/lo [K, N] row-major (bofs tiles, ldsm4t) — NO pre-transpose.
// CTA 128x128, 256 thr, 8 warps (4M x 2N), warp tile 32x64. 3-stage cp.async.
// GEGLU: B cols pre-interleaved (a,g); epilogue writes bf16 hi/lo a*gelu(g), width N/2.
// MODE 0 plain; MODE 1 A gathered via bucket (expert=blockIdx.z), out row off[e]+m;
// MODE 2 A rows off[e]+m, atomicAdd(C[token], w*(acc+bias)).
static constexpr int AT_B  = 16384;                 // one 16 KB tile
static constexpr int NSTG  = 3;
static constexpr int STG_B = 4 * AT_B;              // Ah,Al,Bh,Bl per stage
static constexpr int GSMEM = NSTG * STG_B;          // 196608

template <int MODE, bool GEGLU>
__global__ void __launch_bounds__(256, 1)
fgemm(const __nv_bfloat16* __restrict__ Ah, const __nv_bfloat16* __restrict__ Al,
      const __nv_bfloat16* __restrict__ Bh, const __nv_bfloat16* __restrict__ Bl,
      const float* __restrict__ bias, float* __restrict__ C,
      __nv_bfloat16* __restrict__ OH, __nv_bfloat16* __restrict__ OL,
      int M, int N, int K) {
    extern __shared__ char sm[];
    __shared__ int   sb_tok[128];
    __shared__ float sb_w[128];

    const int tid = threadIdx.x, wid = tid >> 5, lane = tid & 31;
    const int wm = wid & 3, wn = wid >> 2;
    const int row0 = blockIdx.y * 128, col0 = blockIdx.x * 128;

    int e = 0, Me = M, offE = 0;
    if constexpr (MODE != 0) {
        e = blockIdx.z;
        Me = g_cnt[e];
        if (row0 >= Me) return;
        offE = g_off[e];
        Bh += (size_t)e * K * N;
        Bl += (size_t)e * K * N;
        bias += (size_t)e * N;
        if (tid < 128) {
            int r = row0 + tid;
            sb_tok[tid] = (r < Me) ? g_bucket[e * NTOK + r] : 0;
            sb_w[tid]   = (r < Me) ? g_bw[e * NTOK + r] : 0.f;
        }
        __syncthreads();
    }

    const int nch = K >> 6;
    const uint32_t smb = smem_u32(sm);

    auto issue_chunk = [&](int ck) {
        const int k0 = ck << 6;
        const uint32_t base = smb + (ck % NSTG) * STG_B;
        // A tiles (hi/lo): 2048 slots of 16B, 128 rows x 128B, swzA
#pragma unroll
        for (int s = tid; s < 2048; s += 256) {
            int t = s >> 10, slot = s & 1023;
            int r = slot >> 3, cc = slot & 7;
            uint32_t dst = base + t * AT_B + swzA((uint32_t)(r * 128 + cc * 16));
            const __nv_bfloat16* Ab = (t == 0) ? Ah : Al;
            size_t ro = 0; int sz = 16;
            if constexpr (MODE == 1) {
                if (row0 + r < Me) ro = (size_t)sb_tok[r] * K; else sz = 0;
            } else if constexpr (MODE == 2) {
                if (row0 + r < Me) ro = (size_t)(offE + row0 + r) * K; else sz = 0;
            } else {
                ro = (size_t)(row0 + r) * K;
            }
            cp16(dst, Ab + ro + k0 + cc * 8, sz);
        }
        // B tiles (hi/lo): 2048 slots of 16B, 64 k-rows x 256B, bofs
#pragma unroll
        for (int s = tid; s < 2048; s += 256) {
            int t = s >> 10, slot = s & 1023;
            int k = slot >> 4, j16 = slot & 15;
            uint32_t dst = base + (2 + t) * AT_B + bofs(k, j16 * 16);
            const __nv_bfloat16* Bb = (t == 0) ? Bh : Bl;
            cp16(dst, Bb + (size_t)(k0 + k) * N + col0 + j16 * 8, 16);
        }
        CP_COMMIT();
    };

    float acc[2][8][4];
#pragma unroll
    for (int i = 0; i < 2; i++)
#pragma unroll
        for (int j = 0; j < 8; j++)
#pragma unroll
            for (int k = 0; k < 4; k++) acc[i][j][k] = 0.f;

    issue_chunk(0);
    issue_chunk(1);
    for (int ck = 0; ck < nch; ck++) {
        if (ck + 2 < nch) {
            issue_chunk(ck + 2);
            asm volatile("cp.async.wait_group 2;" ::: "memory");
        } else if (ck + 1 < nch) {
            asm volatile("cp.async.wait_group 1;" ::: "memory");
        } else {
            asm volatile("cp.async.wait_group 0;" ::: "memory");
        }
        __syncthreads();

        const uint32_t base = smb + (ck % NSTG) * STG_B;
        const uint32_t tAh = base, tAl = base + AT_B;
        const uint32_t tBh = base + 2 * AT_B, tBl = base + 3 * AT_B;

#pragma unroll
        for (int ks = 0; ks < 4; ks++) {
            uint32_t ahf[2][4], alf[2][4];
#pragma unroll
            for (int mt = 0; mt < 2; mt++) {
                int rrow = wm * 32 + mt * 16 + (lane & 15);
                uint32_t byte = swzA((uint32_t)(rrow * 128 + ks * 32 + (lane >> 4) * 16));
                ldsm4(ahf[mt], tAh + byte);
                ldsm4(alf[mt], tAl + byte);
            }
            const int sub = lane >> 3, i8 = lane & 7;
            const int kk = ks * 16 + (sub & 1) * 8 + i8;
            uint32_t bhf[8][2], blf[8][2];
#pragma unroll
            for (int g = 0; g < 4; g++) {
                int nn = wn * 64 + g * 16 + (sub >> 1) * 8;
                uint32_t byte = bofs(kk, nn * 2);
                uint32_t r4[4];
                ldsm4t(r4, tBh + byte);
                bhf[2 * g][0] = r4[0]; bhf[2 * g][1] = r4[1];
                bhf[2 * g + 1][0] = r4[2]; bhf[2 * g + 1][1] = r4[3];
                ldsm4t(r4, tBl + byte);
                blf[2 * g][0] = r4[0]; blf[2 * g][1] = r4[1];
                blf[2 * g + 1][0] = r4[2]; blf[2 * g + 1][1] = r4[3];
            }
#pragma unroll
            for (int mt = 0; mt < 2; mt++)
#pragma unroll
                for (int nf = 0; nf < 8; nf++) {
                    mma16816(acc[mt][nf], ahf[mt], bhf[nf]);
                    mma16816(acc[mt][nf], ahf[mt], blf[nf]);
                    mma16816(acc[mt][nf], alf[mt], bhf[nf]);
                }
        }
        __syncthreads();
    }

    // ---------------- epilogue ----------------
    const int Hout = N >> 1;
#pragma unroll
    for (int mt = 0; mt < 2; mt++) {
#pragma unroll
        for (int half = 0; half < 2; half++) {
            int ml = wm * 32 + mt * 16 + (lane >> 2) + half * 8;
            if constexpr (MODE != 0) { if (row0 + ml >= Me) continue; }
#pragma unroll
            for (int nf = 0; nf < 8; nf++) {
                int colb = col0 + wn * 64 + nf * 8 + (lane & 3) * 2;
                if constexpr (GEGLU) {
                    int c = colb >> 1;
                    float a = acc[mt][nf][half * 2 + 0] + __ldg(bias + c);
                    float g = acc[mt][nf][half * 2 + 1] + __ldg(bias + Hout + c);
                    float v = a * gelu_exact(g);
                    __nv_bfloat16 vh, vl; split_bf16(v, vh, vl);
                    size_t rr = (MODE != 0) ? (size_t)(offE + row0 + ml)
                                            : (size_t)(row0 + ml);
                    OH[rr * Hout + c] = vh;
                    OL[rr * Hout + c] = vl;
                } else {
                    float v0 = acc[mt][nf][half * 2 + 0] + __ldg(bias + colb + 0);
                    float v1 = acc[mt][nf][half * 2 + 1] + __ldg(bias + colb + 1);
                    if constexpr (MODE == 2) {
                        int tok = sb_tok[ml];
                        float w = sb_w[ml];
                        float* op = C + (size_t)tok * N + colb;
                        atomicAdd(op + 0, w * v0);
                        atomicAdd(op + 1, w * v1);
                    } else {
                        float2* cp = (float2*)(C + (size_t)(row0 + ml) * N + colb);
                        *cp = make_float2(v0, v1);
                    }
                }
            }
        }
    }
}

// ---------------- launch ----------------
extern "C" void kernel_launch(void* const* d_in, const int* in_sizes, int n_in,
                              void* d_out, int out_size) {
    const float* x   = (const float*)d_in[0];
    const float* Ws1 = (const float*)d_in[1];
    const float* bs1 = (const float*)d_in[2];
    const float* Ws2 = (const float*)d_in[3];
    const float* bs2 = (const float*)d_in[4];
    const float* We1 = (const float*)d_in[5];
    const float* be1 = (const float*)d_in[6];
    const float* We2 = (const float*)d_in[7];
    const float* be2 = (const float*)d_in[8];
    const float* Wr  = (const float*)d_in[9];
    const float* br  = (const float*)d_in[10];
    float* out = (float*)d_out;

    cudaFuncSetAttribute(fgemm<0, true>,  cudaFuncAttributeMaxDynamicSharedMemorySize, GSMEM);
    cudaFuncSetAttribute(fgemm<0, false>, cudaFuncAttributeMaxDynamicSharedMemorySize, GSMEM);
    cudaFuncSetAttribute(fgemm<1, true>,  cudaFuncAttributeMaxDynamicSharedMemorySize, GSMEM);
    cudaFuncSetAttribute(fgemm<2, false>, cudaFuncAttributeMaxDynamicSharedMemorySize, GSMEM);

    __nv_bfloat16 *p_xh, *p_xl, *p_ash, *p_asl, *p_arh, *p_arl;
    __nv_bfloat16 *p_w1h, *p_w1l, *p_w2h, *p_w2l, *p_e1h, *p_e1l, *p_e2h, *p_e2l;
    cudaGetSymbolAddress((void**)&p_xh, g_xh);   cudaGetSymbolAddress((void**)&p_xl, g_xl);
    cudaGetSymbolAddress((void**)&p_ash, g_ash); cudaGetSymbolAddress((void**)&p_asl, g_asl);
    cudaGetSymbolAddress((void**)&p_arh, g_arh); cudaGetSymbolAddress((void**)&p_arl, g_arl);
    cudaGetSymbolAddress((void**)&p_w1h, g_w1h); cudaGetSymbolAddress((void**)&p_w1l, g_w1l);
    cudaGetSymbolAddress((void**)&p_w2h, g_w2h); cudaGetSymbolAddress((void**)&p_w2l, g_w2l);
    cudaGetSymbolAddress((void**)&p_e1h, g_e1h); cudaGetSymbolAddress((void**)&p_e1l, g_e1l);
    cudaGetSymbolAddress((void**)&p_e2h, g_e2h); cudaGetSymbolAddress((void**)&p_e2l, g_e2l);

    zero_k<<<1, 32>>>();                                                  // 0
    split_k<<<(NTOK * Dm / 4 + 255) / 256, 256>>>(                        // 1
        (const float4*)x, (uint2*)p_xh, (uint2*)p_xl, NTOK * Dm / 4);
    wsplit_ilv_k<<<dim3((Dm * HSh + 255) / 256, 1), 256>>>(               // 2
        Ws1, p_w1h, p_w1l, Dm, HSh);
    fgemm<0, true><<<dim3(2 * HSh / 128, NTOK / 128), 256, GSMEM>>>(      // 3 (profiled)
        p_xh, p_xl, p_w1h, p_w1l, bs1, nullptr, p_ash, p_asl, NTOK, 2 * HSh, Dm);
    router_k<<<NTOK, 128>>>(x, Wr, br);                                   // 4
    prefix_k<<<1, 1>>>();                                                 // 5
    wsplit_ilv_k<<<dim3((Dm * HRt + 255) / 256, NEXP), 256>>>(            // 6
        We1, p_e1h, p_e1l, Dm, HRt);
    split_k<<<(HSh * Dm / 4 + 255) / 256, 256>>>(                         // 7
        (const float4*)Ws2, (uint2*)p_w2h, (uint2*)p_w2l, HSh * Dm / 4);
    split_k<<<(NEXP * HRt * Dm / 4 + 255) / 256, 256>>>(                  // 8
        (const float4*)We2, (uint2*)p_e2h, (uint2*)p_e2l, NEXP * HRt * Dm / 4);
    fgemm<0, false><<<dim3(Dm / 128, NTOK / 128), 256, GSMEM>>>(          // 9
        p_ash, p_asl, p_w2h, p_w2l, bs2, out, nullptr, nullptr, NTOK, Dm, HSh);
    fgemm<1, true><<<dim3(2 * HRt / 128, NTOK / 128, NEXP), 256, GSMEM>>>( // 10
        p_xh, p_xl, p_e1h, p_e1l, be1, nullptr, p_arh, p_arl, 0, 2 * HRt, Dm);
    fgemm<2, false><<<dim3(Dm / 128, NTOK / 128, NEXP), 256, GSMEM>>>(    // 11
        p_arh, p_arl, p_e2h, p_e2l, be2, out, nullptr, nullptr, 0, Dm, HRt);
}

// round 9
// speedup vs baseline: 1.7604x; 1.0481x over previous
#include <cuda_runtime.h>
#include <cuda_bf16.h>
#include <math.h>
#include <stdint.h>

// ---------------- problem constants ----------------
static constexpr int NTOK = 2048;
static constexpr int Dm   = 1024;
static constexpr int NEXP = 12;
static constexpr int HSh  = 2048;   // shared hidden
static constexpr int HRt  = 3072;   // routed hidden
static constexpr float TAU = 1.5f;

// ---------------- device scratch ----------------
__device__ int   g_cnt[NEXP];
__device__ int   g_off[NEXP];
__device__ int   g_bucket[NEXP * NTOK];
__device__ float g_bw[NEXP * NTOK];

__device__ __nv_bfloat16 g_xh[(size_t)NTOK * Dm],  g_xl[(size_t)NTOK * Dm];
__device__ __nv_bfloat16 g_ash[(size_t)NTOK * HSh], g_asl[(size_t)NTOK * HSh];
__device__ __nv_bfloat16 g_arh[(size_t)2 * NTOK * HRt], g_arl[(size_t)2 * NTOK * HRt];
// converted weights, SAME [K, N] layout as source (W1: a/g column-interleaved)
__device__ __nv_bfloat16 g_w1h[(size_t)Dm * 2 * HSh], g_w1l[(size_t)Dm * 2 * HSh];
__device__ __nv_bfloat16 g_w2h[(size_t)HSh * Dm],     g_w2l[(size_t)HSh * Dm];
__device__ __nv_bfloat16 g_e1h[(size_t)NEXP * Dm * 2 * HRt], g_e1l[(size_t)NEXP * Dm * 2 * HRt];
__device__ __nv_bfloat16 g_e2h[(size_t)NEXP * HRt * Dm],     g_e2l[(size_t)NEXP * HRt * Dm];

// ---------------- helpers ----------------
__device__ __forceinline__ uint32_t smem_u32(const void* p) {
    uint32_t a;
    asm("{ .reg .u64 t; cvta.to.shared.u64 t, %1; cvt.u32.u64 %0, t; }" : "=r"(a) : "l"(p));
    return a;
}
__device__ __forceinline__ uint32_t swzA(uint32_t b) { return b ^ ((b >> 3) & 0x70); }
// B tile: [64 k-rows][64 n-cols bf16] = 128B rows; 16B-granule xor swizzle
__device__ __forceinline__ uint32_t bofs(int k, int nb) {
    return (uint32_t)(k * 128 + (((nb >> 4) ^ (k & 7)) << 4) + (nb & 15));
}

__device__ __forceinline__ void cp16(uint32_t dst, const void* src, int sz) {
    asm volatile("cp.async.cg.shared.global [%0], [%1], 16, %2;"
                 :: "r"(dst), "l"(src), "r"(sz));
}
#define CP_COMMIT() asm volatile("cp.async.commit_group;" ::: "memory")

__device__ __forceinline__ void ldsm4(uint32_t* r, uint32_t addr) {
    asm volatile("ldmatrix.sync.aligned.m8n8.x4.shared.b16 {%0,%1,%2,%3}, [%4];"
                 : "=r"(r[0]), "=r"(r[1]), "=r"(r[2]), "=r"(r[3]) : "r"(addr));
}
__device__ __forceinline__ void ldsm4t(uint32_t* r, uint32_t addr) {
    asm volatile("ldmatrix.sync.aligned.m8n8.x4.trans.shared.b16 {%0,%1,%2,%3}, [%4];"
                 : "=r"(r[0]), "=r"(r[1]), "=r"(r[2]), "=r"(r[3]) : "r"(addr));
}
__device__ __forceinline__ void mma16816(float* c, const uint32_t* a, const uint32_t* b) {
    asm volatile(
        "mma.sync.aligned.m16n8k16.row.col.f32.bf16.bf16.f32 "
        "{%0,%1,%2,%3}, {%4,%5,%6,%7}, {%8,%9}, {%0,%1,%2,%3};"
        : "+f"(c[0]), "+f"(c[1]), "+f"(c[2]), "+f"(c[3])
        : "r"(a[0]), "r"(a[1]), "r"(a[2]), "r"(a[3]), "r"(b[0]), "r"(b[1]));
}
__device__ __forceinline__ void split_bf16(float v, __nv_bfloat16& h, __nv_bfloat16& l) {
    h = __float2bfloat16(v);
    l = __float2bfloat16(v - __bfloat162float(h));
}
__device__ __forceinline__ uint32_t pack2(__nv_bfloat16 a, __nv_bfloat16 b) {
    return (uint32_t)__bfloat16_as_ushort(a) | ((uint32_t)__bfloat16_as_ushort(b) << 16);
}
__device__ __forceinline__ float gelu_exact(float g) {
    return 0.5f * g * (1.0f + erff(g * 0.70710678118654752f));
}

// ---------------- tiny kernels ----------------
__global__ void zero_k() { if (threadIdx.x < NEXP) g_cnt[threadIdx.x] = 0; }

__global__ void prefix_k() {
    if (threadIdx.x == 0) {
        int s = 0;
        for (int e = 0; e < NEXP; e++) { g_off[e] = s; s += g_cnt[e]; }
    }
}

__global__ void router_k(const float* __restrict__ x,
                         const float* __restrict__ Wr,
                         const float* __restrict__ br) {
    int n = blockIdx.x, tid = threadIdx.x;            // 128 threads
    __shared__ float red[128 * NEXP];
    __shared__ float lg[NEXP];
    float part[NEXP];
#pragma unroll
    for (int e = 0; e < NEXP; e++) part[e] = 0.f;
    const float* xr = x + (size_t)n * Dm;
    for (int d = tid; d < Dm; d += 128) {
        float xv = xr[d];
        const float* wr = Wr + (size_t)d * NEXP;
#pragma unroll
        for (int e = 0; e < NEXP; e++) part[e] += xv * wr[e];
    }
#pragma unroll
    for (int e = 0; e < NEXP; e++) red[tid * NEXP + e] = part[e];
    __syncthreads();
    if (tid < NEXP) {
        float s = 0.f;
        for (int i = 0; i < 128; i++) s += red[i * NEXP + tid];
        lg[tid] = (s + br[tid]) / TAU;
    }
    __syncthreads();
    if (tid == 0) {
        int i0 = 0; float v0 = lg[0];
#pragma unroll
        for (int e = 1; e < NEXP; e++) if (lg[e] > v0) { v0 = lg[e]; i0 = e; }
        int i1 = -1; float v1 = -3.4e38f;
#pragma unroll
        for (int e = 0; e < NEXP; e++) if (e != i0 && lg[e] > v1) { v1 = lg[e]; i1 = e; }
        float e1 = __expf(v1 - v0);
        float inv = 1.f / (1.f + e1);
        int s0 = atomicAdd(&g_cnt[i0], 1);
        g_bucket[i0 * NTOK + s0] = n;  g_bw[i0 * NTOK + s0] = inv;
        int s1 = atomicAdd(&g_cnt[i1], 1);
        g_bucket[i1 * NTOK + s1] = n;  g_bw[i1 * NTOK + s1] = e1 * inv;
    }
}

// vectorized split fp32 -> bf16 hi/lo (layout-preserving, n multiple of 4)
__global__ void split_k(const float4* __restrict__ s, uint2* __restrict__ dh,
                        uint2* __restrict__ dl, int n4) {
    int i = blockIdx.x * 256 + threadIdx.x;
    if (i >= n4) return;
    float4 v = s[i];
    __nv_bfloat16 h[4], l[4];
    split_bf16(v.x, h[0], l[0]); split_bf16(v.y, h[1], l[1]);
    split_bf16(v.z, h[2], l[2]); split_bf16(v.w, h[3], l[3]);
    dh[i] = make_uint2(pack2(h[0], h[1]), pack2(h[2], h[3]));
    dl[i] = make_uint2(pack2(l[0], l[1]), pack2(l[2], l[3]));
}

// W1 conversion: fp32 [K, 2H] -> bf16 hi/lo [K, 2H] with a/g column interleave
__global__ void wsplit_ilv_k(const float* __restrict__ W, __nv_bfloat16* __restrict__ oh,
                             __nv_bfloat16* __restrict__ ol, int K, int H) {
    int i = blockIdx.x * 256 + threadIdx.x;
    if (i >= K * H) return;
    int k = i / H, c = i - k * H;
    size_t zo = (size_t)blockIdx.y * K * 2 * H;
    const float* wr = W + zo + (size_t)k * 2 * H;
    float a = wr[c], g = wr[H + c];
    __nv_bfloat16 ah, al, gh, gl;
    split_bf16(a, ah, al); split_bf16(g, gh, gl);
    size_t o = zo + (size_t)k * 2 * H + 2 * c;
    *(uint32_t*)(oh + o) = pack2(ah, gh);
    *(uint32_t*)(ol + o) = pack2(al, gl);
}

// ---------------- HMMA bf16x3 GEMM ----------------
// CTA 128M x 64N, 256 thr, 8 warps (4M x 2N), warp tile 32x32, 2 CTAs/SM.
// A: bf16 hi/lo [M,K] (swzA, ldsm4). B: bf16 hi/lo [K,N] (bofs, ldsm4t).
// 2-stage cp.async. GEGLU: interleaved a/g cols, epilogue writes bf16 hi/lo.
// MODE 0 plain; MODE 1 A via bucket (expert=blockIdx.z), out row off[e]+m;
// MODE 2 A rows off[e]+m, atomicAdd(C[token], w*(acc+bias)).
static constexpr int AT_B  = 16384;                 // A tile 128x64x2B
static constexpr int BT_B  = 8192;                  // B tile 64x64x2B
static constexpr int STG_B = 2 * AT_B + 2 * BT_B;   // 49152
static constexpr int GSMEM = 2 * STG_B;             // 98304

template <int MODE, bool GEGLU>
__global__ void __launch_bounds__(256, 2)
fgemm(const __nv_bfloat16* __restrict__ Ah, const __nv_bfloat16* __restrict__ Al,
      const __nv_bfloat16* __restrict__ Bh, const __nv_bfloat16* __restrict__ Bl,
      const float* __restrict__ bias, float* __restrict__ C,
      __nv_bfloat16* __restrict__ OH, __nv_bfloat16* __restrict__ OL,
      int M, int N, int K) {
    extern __shared__ char sm[];
    __shared__ int   sb_tok[128];
    __shared__ float sb_w[128];

    const int tid = threadIdx.x, wid = tid >> 5, lane = tid & 31;
    const int wm = wid & 3, wn = wid >> 2;
    const int row0 = blockIdx.y * 128, col0 = blockIdx.x * 64;

    int e = 0, Me = M, offE = 0;
    if constexpr (MODE != 0) {
        e = blockIdx.z;
        Me = g_cnt[e];
        if (row0 >= Me) return;
        offE = g_off[e];
        Bh += (size_t)e * K * N;
        Bl += (size_t)e * K * N;
        bias += (size_t)e * N;
        if (tid < 128) {
            int r = row0 + tid;
            sb_tok[tid] = (r < Me) ? g_bucket[e * NTOK + r] : 0;
            sb_w[tid]   = (r < Me) ? g_bw[e * NTOK + r] : 0.f;
        }
        __syncthreads();
    }

    const int nch = K >> 6;
    const uint32_t smb = smem_u32(sm);

    auto issue_chunk = [&](int ck) {
        const int k0 = ck << 6;
        const uint32_t base = smb + (ck & 1) * STG_B;
        // A tiles (hi/lo): 2048 slots of 16B, 128 rows x 128B, swzA
#pragma unroll
        for (int s = tid; s < 2048; s += 256) {
            int t = s >> 10, slot = s & 1023;
            int r = slot >> 3, cc = slot & 7;
            uint32_t dst = base + t * AT_B + swzA((uint32_t)(r * 128 + cc * 16));
            const __nv_bfloat16* Ab = (t == 0) ? Ah : Al;
            size_t ro = 0; int sz = 16;
            if constexpr (MODE == 1) {
                if (row0 + r < Me) ro = (size_t)sb_tok[r] * K; else sz = 0;
            } else if constexpr (MODE == 2) {
                if (row0 + r < Me) ro = (size_t)(offE + row0 + r) * K; else sz = 0;
            } else {
                ro = (size_t)(row0 + r) * K;
            }
            cp16(dst, Ab + ro + k0 + cc * 8, sz);
        }
        // B tiles (hi/lo): 1024 slots of 16B, 64 k-rows x 128B, bofs
#pragma unroll
        for (int s = tid; s < 1024; s += 256) {
            int t = s >> 9, slot = s & 511;
            int k = slot >> 3, j16 = slot & 7;
            uint32_t dst = base + 2 * AT_B + t * BT_B + bofs(k, j16 * 16);
            const __nv_bfloat16* Bb = (t == 0) ? Bh : Bl;
            cp16(dst, Bb + (size_t)(k0 + k) * N + col0 + j16 * 8, 16);
        }
        CP_COMMIT();
    };

    float acc[2][4][4];
#pragma unroll
    for (int i = 0; i < 2; i++)
#pragma unroll
        for (int j = 0; j < 4; j++)
#pragma unroll
            for (int k = 0; k < 4; k++) acc[i][j][k] = 0.f;

    issue_chunk(0);
    for (int ck = 0; ck < nch; ck++) {
        if (ck + 1 < nch) {
            issue_chunk(ck + 1);
            asm volatile("cp.async.wait_group 1;" ::: "memory");
        } else {
            asm volatile("cp.async.wait_group 0;" ::: "memory");
        }
        __syncthreads();

        const uint32_t base = smb + (ck & 1) * STG_B;
        const uint32_t tAh = base, tAl = base + AT_B;
        const uint32_t tBh = base + 2 * AT_B, tBl = tBh + BT_B;

#pragma unroll
        for (int ks = 0; ks < 4; ks++) {
            uint32_t ahf[2][4], alf[2][4];
#pragma unroll
            for (int mt = 0; mt < 2; mt++) {
                int rrow = wm * 32 + mt * 16 + (lane & 15);
                uint32_t byte = swzA((uint32_t)(rrow * 128 + ks * 32 + (lane >> 4) * 16));
                ldsm4(ahf[mt], tAh + byte);
                ldsm4(alf[mt], tAl + byte);
            }
            const int sub = lane >> 3, i8 = lane & 7;
            const int kk = ks * 16 + (sub & 1) * 8 + i8;
            uint32_t bhf[4][2], blf[4][2];
#pragma unroll
            for (int g = 0; g < 2; g++) {
                int nn = wn * 32 + g * 16 + (sub >> 1) * 8;
                uint32_t byte = bofs(kk, nn * 2);
                uint32_t r4[4];
                ldsm4t(r4, tBh + byte);
                bhf[2 * g][0] = r4[0]; bhf[2 * g][1] = r4[1];
                bhf[2 * g + 1][0] = r4[2]; bhf[2 * g + 1][1] = r4[3];
                ldsm4t(r4, tBl + byte);
                blf[2 * g][0] = r4[0]; blf[2 * g][1] = r4[1];
                blf[2 * g + 1][0] = r4[2]; blf[2 * g + 1][1] = r4[3];
            }
#pragma unroll
            for (int mt = 0; mt < 2; mt++)
#pragma unroll
                for (int nf = 0; nf < 4; nf++) {
                    mma16816(acc[mt][nf], ahf[mt], bhf[nf]);
                    mma16816(acc[mt][nf], ahf[mt], blf[nf]);
                    mma16816(acc[mt][nf], alf[mt], bhf[nf]);
                }
        }
        __syncthreads();
    }

    // ---------------- epilogue ----------------
    const int Hout = N >> 1;
#pragma unroll
    for (int mt = 0; mt < 2; mt++) {
#pragma unroll
        for (int half = 0; half < 2; half++) {
            int ml = wm * 32 + mt * 16 + (lane >> 2) + half * 8;
            if constexpr (MODE != 0) { if (row0 + ml >= Me) continue; }
#pragma unroll
            for (int nf = 0; nf < 4; nf++) {
                int colb = col0 + wn * 32 + nf * 8 + (lane & 3) * 2;
                if constexpr (GEGLU) {
                    int c = colb >> 1;
                    float a = acc[mt][nf][half * 2 + 0] + __ldg(bias + c);
                    float g = acc[mt][nf][half * 2 + 1] + __ldg(bias + Hout + c);
                    float v = a * gelu_exact(g);
                    __nv_bfloat16 vh, vl; split_bf16(v, vh, vl);
                    size_t rr = (MODE != 0) ? (size_t)(offE + row0 + ml)
                                            : (size_t)(row0 + ml);
                    OH[rr * Hout + c] = vh;
                    OL[rr * Hout + c] = vl;
                } else {
                    float v0 = acc[mt][nf][half * 2 + 0] + __ldg(bias + colb + 0);
                    float v1 = acc[mt][nf][half * 2 + 1] + __ldg(bias + colb + 1);
                    if constexpr (MODE == 2) {
                        int tok = sb_tok[ml];
                        float w = sb_w[ml];
                        float* op = C + (size_t)tok * N + colb;
                        atomicAdd(op + 0, w * v0);
                        atomicAdd(op + 1, w * v1);
                    } else {
                        float2* cp = (float2*)(C + (size_t)(row0 + ml) * N + colb);
                        *cp = make_float2(v0, v1);
                    }
                }
            }
        }
    }
}

// ---------------- launch ----------------
extern "C" void kernel_launch(void* const* d_in, const int* in_sizes, int n_in,
                              void* d_out, int out_size) {
    const float* x   = (const float*)d_in[0];
    const float* Ws1 = (const float*)d_in[1];
    const float* bs1 = (const float*)d_in[2];
    const float* Ws2 = (const float*)d_in[3];
    const float* bs2 = (const float*)d_in[4];
    const float* We1 = (const float*)d_in[5];
    const float* be1 = (const float*)d_in[6];
    const float* We2 = (const float*)d_in[7];
    const float* be2 = (const float*)d_in[8];
    const float* Wr  = (const float*)d_in[9];
    const float* br  = (const float*)d_in[10];
    float* out = (float*)d_out;

    cudaFuncSetAttribute(fgemm<0, true>,  cudaFuncAttributeMaxDynamicSharedMemorySize, GSMEM);
    cudaFuncSetAttribute(fgemm<0, false>, cudaFuncAttributeMaxDynamicSharedMemorySize, GSMEM);
    cudaFuncSetAttribute(fgemm<1, true>,  cudaFuncAttributeMaxDynamicSharedMemorySize, GSMEM);
    cudaFuncSetAttribute(fgemm<2, false>, cudaFuncAttributeMaxDynamicSharedMemorySize, GSMEM);

    __nv_bfloat16 *p_xh, *p_xl, *p_ash, *p_asl, *p_arh, *p_arl;
    __nv_bfloat16 *p_w1h, *p_w1l, *p_w2h, *p_w2l, *p_e1h, *p_e1l, *p_e2h, *p_e2l;
    cudaGetSymbolAddress((void**)&p_xh, g_xh);   cudaGetSymbolAddress((void**)&p_xl, g_xl);
    cudaGetSymbolAddress((void**)&p_ash, g_ash); cudaGetSymbolAddress((void**)&p_asl, g_asl);
    cudaGetSymbolAddress((void**)&p_arh, g_arh); cudaGetSymbolAddress((void**)&p_arl, g_arl);
    cudaGetSymbolAddress((void**)&p_w1h, g_w1h); cudaGetSymbolAddress((void**)&p_w1l, g_w1l);
    cudaGetSymbolAddress((void**)&p_w2h, g_w2h); cudaGetSymbolAddress((void**)&p_w2l, g_w2l);
    cudaGetSymbolAddress((void**)&p_e1h, g_e1h); cudaGetSymbolAddress((void**)&p_e1l, g_e1l);
    cudaGetSymbolAddress((void**)&p_e2h, g_e2h); cudaGetSymbolAddress((void**)&p_e2l, g_e2l);

    zero_k<<<1, 32>>>();                                                  // 0
    split_k<<<(NTOK * Dm / 4 + 255) / 256, 256>>>(                        // 1
        (const float4*)x, (uint2*)p_xh, (uint2*)p_xl, NTOK * Dm / 4);
    wsplit_ilv_k<<<dim3((Dm * HSh + 255) / 256, 1), 256>>>(               // 2
        Ws1, p_w1h, p_w1l, Dm, HSh);
    fgemm<0, true><<<dim3(2 * HSh / 64, NTOK / 128), 256, GSMEM>>>(       // 3 (profiled)
        p_xh, p_xl, p_w1h, p_w1l, bs1, nullptr, p_ash, p_asl, NTOK, 2 * HSh, Dm);
    router_k<<<NTOK, 128>>>(x, Wr, br);                                   // 4
    prefix_k<<<1, 1>>>();                                                 // 5
    wsplit_ilv_k<<<dim3((Dm * HRt + 255) / 256, NEXP), 256>>>(            // 6
        We1, p_e1h, p_e1l, Dm, HRt);
    split_k<<<(HSh * Dm / 4 + 255) / 256, 256>>>(                         // 7
        (const float4*)Ws2, (uint2*)p_w2h, (uint2*)p_w2l, HSh * Dm / 4);
    split_k<<<(NEXP * HRt * Dm / 4 + 255) / 256, 256>>>(                  // 8
        (const float4*)We2, (uint2*)p_e2h, (uint2*)p_e2l, NEXP * HRt * Dm / 4);
    fgemm<0, false><<<dim3(Dm / 64, NTOK / 128), 256, GSMEM>>>(           // 9
        p_ash, p_asl, p_w2h, p_w2l, bs2, out, nullptr, nullptr, NTOK, Dm, HSh);
    fgemm<1, true><<<dim3(2 * HRt / 64, NTOK / 128, NEXP), 256, GSMEM>>>( // 10
        p_xh, p_xl, p_e1h, p_e1l, be1, nullptr, p_arh, p_arl, 0, 2 * HRt, Dm);
    fgemm<2, false><<<dim3(Dm / 64, NTOK / 128, NEXP), 256, GSMEM>>>(     // 11
        p_arh, p_arl, p_e2h, p_e2l, be2, out, nullptr, nullptr, 0, Dm, HRt);
}

// round 10
// speedup vs baseline: 1.8273x; 1.0380x over previous
#include <cuda_runtime.h>
#include <cuda_bf16.h>
#include <math.h>
#include <stdint.h>

// ---------------- problem constants ----------------
static constexpr int NTOK = 2048;
static constexpr int Dm   = 1024;
static constexpr int NEXP = 12;
static constexpr int HSh  = 2048;   // shared hidden
static constexpr int HRt  = 3072;   // routed hidden
static constexpr float TAU = 1.5f;

// ---------------- device scratch ----------------
__device__ int   g_cnt[NEXP];
__device__ int   g_off[NEXP];
__device__ int   g_bucket[NEXP * NTOK];
__device__ float g_bw[NEXP * NTOK];

__device__ __nv_bfloat16 g_xh[(size_t)NTOK * Dm],  g_xl[(size_t)NTOK * Dm];
__device__ __nv_bfloat16 g_ash[(size_t)NTOK * HSh], g_asl[(size_t)NTOK * HSh];
__device__ __nv_bfloat16 g_arh[(size_t)2 * NTOK * HRt], g_arl[(size_t)2 * NTOK * HRt];
// converted weights, SAME [K, N] layout as source (W1: a/g column-interleaved)
__device__ __nv_bfloat16 g_w1h[(size_t)Dm * 2 * HSh], g_w1l[(size_t)Dm * 2 * HSh];
__device__ __nv_bfloat16 g_w2h[(size_t)HSh * Dm],     g_w2l[(size_t)HSh * Dm];
__device__ __nv_bfloat16 g_e1h[(size_t)NEXP * Dm * 2 * HRt], g_e1l[(size_t)NEXP * Dm * 2 * HRt];
__device__ __nv_bfloat16 g_e2h[(size_t)NEXP * HRt * Dm],     g_e2l[(size_t)NEXP * HRt * Dm];

// ---------------- helpers ----------------
__device__ __forceinline__ uint32_t smem_u32(const void* p) {
    uint32_t a;
    asm("{ .reg .u64 t; cvta.to.shared.u64 t, %1; cvt.u32.u64 %0, t; }" : "=r"(a) : "l"(p));
    return a;
}
__device__ __forceinline__ uint32_t swzA(uint32_t b) { return b ^ ((b >> 3) & 0x70); }
// B tile: [64 k-rows][64 n-cols bf16] = 128B rows; 16B-granule xor swizzle
__device__ __forceinline__ uint32_t bofs(int k, int nb) {
    return (uint32_t)(k * 128 + (((nb >> 4) ^ (k & 7)) << 4) + (nb & 15));
}

__device__ __forceinline__ void cp16(uint32_t dst, const void* src, int sz) {
    asm volatile("cp.async.cg.shared.global [%0], [%1], 16, %2;"
                 :: "r"(dst), "l"(src), "r"(sz));
}
#define CP_COMMIT() asm volatile("cp.async.commit_group;" ::: "memory")

__device__ __forceinline__ void ldsm4(uint32_t* r, uint32_t addr) {
    asm volatile("ldmatrix.sync.aligned.m8n8.x4.shared.b16 {%0,%1,%2,%3}, [%4];"
                 : "=r"(r[0]), "=r"(r[1]), "=r"(r[2]), "=r"(r[3]) : "r"(addr));
}
__device__ __forceinline__ void ldsm4t(uint32_t* r, uint32_t addr) {
    asm volatile("ldmatrix.sync.aligned.m8n8.x4.trans.shared.b16 {%0,%1,%2,%3}, [%4];"
                 : "=r"(r[0]), "=r"(r[1]), "=r"(r[2]), "=r"(r[3]) : "r"(addr));
}
__device__ __forceinline__ void mma16816(float* c, const uint32_t* a, const uint32_t* b) {
    asm volatile(
        "mma.sync.aligned.m16n8k16.row.col.f32.bf16.bf16.f32 "
        "{%0,%1,%2,%3}, {%4,%5,%6,%7}, {%8,%9}, {%0,%1,%2,%3};"
        : "+f"(c[0]), "+f"(c[1]), "+f"(c[2]), "+f"(c[3])
        : "r"(a[0]), "r"(a[1]), "r"(a[2]), "r"(a[3]), "r"(b[0]), "r"(b[1]));
}
__device__ __forceinline__ void split_bf16(float v, __nv_bfloat16& h, __nv_bfloat16& l) {
    h = __float2bfloat16(v);
    l = __float2bfloat16(v - __bfloat162float(h));
}
__device__ __forceinline__ uint32_t pack2(__nv_bfloat16 a, __nv_bfloat16 b) {
    return (uint32_t)__bfloat16_as_ushort(a) | ((uint32_t)__bfloat16_as_ushort(b) << 16);
}
__device__ __forceinline__ float gelu_exact(float g) {
    return 0.5f * g * (1.0f + erff(g * 0.70710678118654752f));
}

// ---------------- tiny kernels ----------------
__global__ void zero_k() { if (threadIdx.x < NEXP) g_cnt[threadIdx.x] = 0; }

__global__ void prefix_k() {
    if (threadIdx.x == 0) {
        int s = 0;
        for (int e = 0; e < NEXP; e++) { g_off[e] = s; s += g_cnt[e]; }
    }
}

__global__ void router_k(const float* __restrict__ x,
                         const float* __restrict__ Wr,
                         const float* __restrict__ br) {
    int n = blockIdx.x, tid = threadIdx.x;            // 128 threads
    __shared__ float red[128 * NEXP];
    __shared__ float lg[NEXP];
    float part[NEXP];
#pragma unroll
    for (int e = 0; e < NEXP; e++) part[e] = 0.f;
    const float* xr = x + (size_t)n * Dm;
    for (int d = tid; d < Dm; d += 128) {
        float xv = xr[d];
        const float* wr = Wr + (size_t)d * NEXP;
#pragma unroll
        for (int e = 0; e < NEXP; e++) part[e] += xv * wr[e];
    }
#pragma unroll
    for (int e = 0; e < NEXP; e++) red[tid * NEXP + e] = part[e];
    __syncthreads();
    if (tid < NEXP) {
        float s = 0.f;
        for (int i = 0; i < 128; i++) s += red[i * NEXP + tid];
        lg[tid] = (s + br[tid]) / TAU;
    }
    __syncthreads();
    if (tid == 0) {
        int i0 = 0; float v0 = lg[0];
#pragma unroll
        for (int e = 1; e < NEXP; e++) if (lg[e] > v0) { v0 = lg[e]; i0 = e; }
        int i1 = -1; float v1 = -3.4e38f;
#pragma unroll
        for (int e = 0; e < NEXP; e++) if (e != i0 && lg[e] > v1) { v1 = lg[e]; i1 = e; }
        float e1 = __expf(v1 - v0);
        float inv = 1.f / (1.f + e1);
        int s0 = atomicAdd(&g_cnt[i0], 1);
        g_bucket[i0 * NTOK + s0] = n;  g_bw[i0 * NTOK + s0] = inv;
        int s1 = atomicAdd(&g_cnt[i1], 1);
        g_bucket[i1 * NTOK + s1] = n;  g_bw[i1 * NTOK + s1] = e1 * inv;
    }
}

// vectorized split fp32 -> bf16 hi/lo (layout-preserving, n multiple of 4)
__global__ void split_k(const float4* __restrict__ s, uint2* __restrict__ dh,
                        uint2* __restrict__ dl, int n4) {
    int i = blockIdx.x * 256 + threadIdx.x;
    if (i >= n4) return;
    float4 v = s[i];
    __nv_bfloat16 h[4], l[4];
    split_bf16(v.x, h[0], l[0]); split_bf16(v.y, h[1], l[1]);
    split_bf16(v.z, h[2], l[2]); split_bf16(v.w, h[3], l[3]);
    dh[i] = make_uint2(pack2(h[0], h[1]), pack2(h[2], h[3]));
    dl[i] = make_uint2(pack2(l[0], l[1]), pack2(l[2], l[3]));
}

// W1 conversion: fp32 [K, 2H] -> bf16 hi/lo [K, 2H] with a/g column interleave
__global__ void wsplit_ilv_k(const float* __restrict__ W, __nv_bfloat16* __restrict__ oh,
                             __nv_bfloat16* __restrict__ ol, int K, int H) {
    int i = blockIdx.x * 256 + threadIdx.x;
    if (i >= K * H) return;
    int k = i / H, c = i - k * H;
    size_t zo = (size_t)blockIdx.y * K * 2 * H;
    const float* wr = W + zo + (size_t)k * 2 * H;
    float a = wr[c], g = wr[H + c];
    __nv_bfloat16 ah, al, gh, gl;
    split_bf16(a, ah, al); split_bf16(g, gh, gl);
    size_t o = zo + (size_t)k * 2 * H + 2 * c;
    *(uint32_t*)(oh + o) = pack2(ah, gh);
    *(uint32_t*)(ol + o) = pack2(al, gl);
}

// ---------------- HMMA bf16x3 GEMM ----------------
// CTA 128M x 64N, 256 thr, 8 warps (4M x 2N), warp tile 32x32, 2 CTAs/SM.
// A: bf16 hi/lo [M,K] (swzA, ldsm4). B: bf16 hi/lo [K,N] (bofs, ldsm4t).
// 2-stage cp.async. GEGLU: interleaved a/g cols, epilogue writes bf16 hi/lo.
// MODE 0 plain; MODE 1 A via bucket (expert=blockIdx.z), out row off[e]+m;
// MODE 2 A rows off[e]+m, atomicAdd(C[token], w*(acc+bias)).
static constexpr int AT_B  = 16384;                 // A tile 128x64x2B
static constexpr int BT_B  = 8192;                  // B tile 64x64x2B
static constexpr int STG_B = 2 * AT_B + 2 * BT_B;   // 49152
static constexpr int GSMEM = 2 * STG_B;             // 98304

template <int MODE, bool GEGLU>
__global__ void __launch_bounds__(256, 2)
fgemm(const __nv_bfloat16* __restrict__ Ah, const __nv_bfloat16* __restrict__ Al,
      const __nv_bfloat16* __restrict__ Bh, const __nv_bfloat16* __restrict__ Bl,
      const float* __restrict__ bias, float* __restrict__ C,
      __nv_bfloat16* __restrict__ OH, __nv_bfloat16* __restrict__ OL,
      int M, int N, int K) {
    extern __shared__ char sm[];
    __shared__ int   sb_tok[128];
    __shared__ float sb_w[128];

    const int tid = threadIdx.x, wid = tid >> 5, lane = tid & 31;
    const int wm = wid & 3, wn = wid >> 2;
    const int row0 = blockIdx.y * 128, col0 = blockIdx.x * 64;

    int e = 0, Me = M, offE = 0;
    if constexpr (MODE != 0) {
        e = blockIdx.z;
        Me = g_cnt[e];
        if (row0 >= Me) return;
        offE = g_off[e];
        Bh += (size_t)e * K * N;
        Bl += (size_t)e * K * N;
        bias += (size_t)e * N;
        if (tid < 128) {
            int r = row0 + tid;
            sb_tok[tid] = (r < Me) ? g_bucket[e * NTOK + r] : 0;
            sb_w[tid]   = (r < Me) ? g_bw[e * NTOK + r] : 0.f;
        }
        __syncthreads();
    }

    const int nch = K >> 6;
    const uint32_t smb = smem_u32(sm);

    auto issue_chunk = [&](int ck) {
        const int k0 = ck << 6;
        const uint32_t base = smb + (ck & 1) * STG_B;
#pragma unroll
        for (int s = tid; s < 2048; s += 256) {
            int t = s >> 10, slot = s & 1023;
            int r = slot >> 3, cc = slot & 7;
            uint32_t dst = base + t * AT_B + swzA((uint32_t)(r * 128 + cc * 16));
            const __nv_bfloat16* Ab = (t == 0) ? Ah : Al;
            size_t ro = 0; int sz = 16;
            if constexpr (MODE == 1) {
                if (row0 + r < Me) ro = (size_t)sb_tok[r] * K; else sz = 0;
            } else if constexpr (MODE == 2) {
                if (row0 + r < Me) ro = (size_t)(offE + row0 + r) * K; else sz = 0;
            } else {
                ro = (size_t)(row0 + r) * K;
            }
            cp16(dst, Ab + ro + k0 + cc * 8, sz);
        }
#pragma unroll
        for (int s = tid; s < 1024; s += 256) {
            int t = s >> 9, slot = s & 511;
            int k = slot >> 3, j16 = slot & 7;
            uint32_t dst = base + 2 * AT_B + t * BT_B + bofs(k, j16 * 16);
            const __nv_bfloat16* Bb = (t == 0) ? Bh : Bl;
            cp16(dst, Bb + (size_t)(k0 + k) * N + col0 + j16 * 8, 16);
        }
        CP_COMMIT();
    };

    float acc[2][4][4];
#pragma unroll
    for (int i = 0; i < 2; i++)
#pragma unroll
        for (int j = 0; j < 4; j++)
#pragma unroll
            for (int k = 0; k < 4; k++) acc[i][j][k] = 0.f;

    issue_chunk(0);
    for (int ck = 0; ck < nch; ck++) {
        if (ck + 1 < nch) {
            issue_chunk(ck + 1);
            asm volatile("cp.async.wait_group 1;" ::: "memory");
        } else {
            asm volatile("cp.async.wait_group 0;" ::: "memory");
        }
        __syncthreads();

        const uint32_t base = smb + (ck & 1) * STG_B;
        const uint32_t tAh = base, tAl = base + AT_B;
        const uint32_t tBh = base + 2 * AT_B, tBl = tBh + BT_B;

#pragma unroll
        for (int ks = 0; ks < 4; ks++) {
            uint32_t ahf[2][4], alf[2][4];
#pragma unroll
            for (int mt = 0; mt < 2; mt++) {
                int rrow = wm * 32 + mt * 16 + (lane & 15);
                uint32_t byte = swzA((uint32_t)(rrow * 128 + ks * 32 + (lane >> 4) * 16));
                ldsm4(ahf[mt], tAh + byte);
                ldsm4(alf[mt], tAl + byte);
            }
            const int sub = lane >> 3, i8 = lane & 7;
            const int kk = ks * 16 + (sub & 1) * 8 + i8;
            uint32_t bhf[4][2], blf[4][2];
#pragma unroll
            for (int g = 0; g < 2; g++) {
                int nn = wn * 32 + g * 16 + (sub >> 1) * 8;
                uint32_t byte = bofs(kk, nn * 2);
                uint32_t r4[4];
                ldsm4t(r4, tBh + byte);
                bhf[2 * g][0] = r4[0]; bhf[2 * g][1] = r4[1];
                bhf[2 * g + 1][0] = r4[2]; bhf[2 * g + 1][1] = r4[3];
                ldsm4t(r4, tBl + byte);
                blf[2 * g][0] = r4[0]; blf[2 * g][1] = r4[1];
                blf[2 * g + 1][0] = r4[2]; blf[2 * g + 1][1] = r4[3];
            }
#pragma unroll
            for (int mt = 0; mt < 2; mt++)
#pragma unroll
                for (int nf = 0; nf < 4; nf++) {
                    mma16816(acc[mt][nf], ahf[mt], bhf[nf]);
                    mma16816(acc[mt][nf], ahf[mt], blf[nf]);
                    mma16816(acc[mt][nf], alf[mt], bhf[nf]);
                }
        }
        __syncthreads();
    }

    // ---------------- epilogue ----------------
    const int Hout = N >> 1;
#pragma unroll
    for (int mt = 0; mt < 2; mt++) {
#pragma unroll
        for (int half = 0; half < 2; half++) {
            int ml = wm * 32 + mt * 16 + (lane >> 2) + half * 8;
            if constexpr (MODE != 0) { if (row0 + ml >= Me) continue; }
#pragma unroll
            for (int nf = 0; nf < 4; nf++) {
                int colb = col0 + wn * 32 + nf * 8 + (lane & 3) * 2;
                if constexpr (GEGLU) {
                    int c = colb >> 1;
                    float a = acc[mt][nf][half * 2 + 0] + __ldg(bias + c);
                    float g = acc[mt][nf][half * 2 + 1] + __ldg(bias + Hout + c);
                    float v = a * gelu_exact(g);
                    __nv_bfloat16 vh, vl; split_bf16(v, vh, vl);
                    size_t rr = (MODE != 0) ? (size_t)(offE + row0 + ml)
                                            : (size_t)(row0 + ml);
                    OH[rr * Hout + c] = vh;
                    OL[rr * Hout + c] = vl;
                } else {
                    float v0 = acc[mt][nf][half * 2 + 0] + __ldg(bias + colb + 0);
                    float v1 = acc[mt][nf][half * 2 + 1] + __ldg(bias + colb + 1);
                    if constexpr (MODE == 2) {
                        int tok = sb_tok[ml];
                        float w = sb_w[ml];
                        float* op = C + (size_t)tok * N + colb;
                        atomicAdd(op + 0, w * v0);
                        atomicAdd(op + 1, w * v1);
                    } else {
                        float2* cp = (float2*)(C + (size_t)(row0 + ml) * N + colb);
                        *cp = make_float2(v0, v1);
                    }
                }
            }
        }
    }
}

// ---------------- launch ----------------
extern "C" void kernel_launch(void* const* d_in, const int* in_sizes, int n_in,
                              void* d_out, int out_size) {
    const float* x   = (const float*)d_in[0];
    const float* Ws1 = (const float*)d_in[1];
    const float* bs1 = (const float*)d_in[2];
    const float* Ws2 = (const float*)d_in[3];
    const float* bs2 = (const float*)d_in[4];
    const float* We1 = (const float*)d_in[5];
    const float* be1 = (const float*)d_in[6];
    const float* We2 = (const float*)d_in[7];
    const float* be2 = (const float*)d_in[8];
    const float* Wr  = (const float*)d_in[9];
    const float* br  = (const float*)d_in[10];
    float* out = (float*)d_out;

    cudaFuncSetAttribute(fgemm<0, true>,  cudaFuncAttributeMaxDynamicSharedMemorySize, GSMEM);
    cudaFuncSetAttribute(fgemm<0, false>, cudaFuncAttributeMaxDynamicSharedMemorySize, GSMEM);
    cudaFuncSetAttribute(fgemm<1, true>,  cudaFuncAttributeMaxDynamicSharedMemorySize, GSMEM);
    cudaFuncSetAttribute(fgemm<2, false>, cudaFuncAttributeMaxDynamicSharedMemorySize, GSMEM);

    __nv_bfloat16 *p_xh, *p_xl, *p_ash, *p_asl, *p_arh, *p_arl;
    __nv_bfloat16 *p_w1h, *p_w1l, *p_w2h, *p_w2l, *p_e1h, *p_e1l, *p_e2h, *p_e2l;
    cudaGetSymbolAddress((void**)&p_xh, g_xh);   cudaGetSymbolAddress((void**)&p_xl, g_xl);
    cudaGetSymbolAddress((void**)&p_ash, g_ash); cudaGetSymbolAddress((void**)&p_asl, g_asl);
    cudaGetSymbolAddress((void**)&p_arh, g_arh); cudaGetSymbolAddress((void**)&p_arl, g_arl);
    cudaGetSymbolAddress((void**)&p_w1h, g_w1h); cudaGetSymbolAddress((void**)&p_w1l, g_w1l);
    cudaGetSymbolAddress((void**)&p_w2h, g_w2h); cudaGetSymbolAddress((void**)&p_w2l, g_w2l);
    cudaGetSymbolAddress((void**)&p_e1h, g_e1h); cudaGetSymbolAddress((void**)&p_e1l, g_e1l);
    cudaGetSymbolAddress((void**)&p_e2h, g_e2h); cudaGetSymbolAddress((void**)&p_e2l, g_e2l);

    // one-time host resources (streams/events are host-side; no device alloc)
    static cudaStream_t sB = nullptr;
    static cudaEvent_t  evF = nullptr, evJ = nullptr;
    if (!sB) {
        cudaStreamCreateWithFlags(&sB, cudaStreamNonBlocking);
        cudaEventCreateWithFlags(&evF, cudaEventDisableTiming);
        cudaEventCreateWithFlags(&evJ, cudaEventDisableTiming);
    }

    // --- common prefix on origin stream ---
    split_k<<<(NTOK * Dm / 4 + 255) / 256, 256>>>(
        (const float4*)x, (uint2*)p_xh, (uint2*)p_xl, NTOK * Dm / 4);
    zero_k<<<1, 32>>>();

    // fork
    cudaEventRecord(evF, 0);
    cudaStreamWaitEvent(sB, evF, 0);

    // --- Branch B (stream sB): routing + expert weight conversion + routed GEMM1 ---
    router_k<<<NTOK, 128, 0, sB>>>(x, Wr, br);
    prefix_k<<<1, 1, 0, sB>>>();
    wsplit_ilv_k<<<dim3((Dm * HRt + 255) / 256, NEXP), 256, 0, sB>>>(
        We1, p_e1h, p_e1l, Dm, HRt);
    split_k<<<(NEXP * HRt * Dm / 4 + 255) / 256, 256, 0, sB>>>(
        (const float4*)We2, (uint2*)p_e2h, (uint2*)p_e2l, NEXP * HRt * Dm / 4);
    fgemm<1, true><<<dim3(2 * HRt / 64, NTOK / 128, NEXP), 256, GSMEM, sB>>>(
        p_xh, p_xl, p_e1h, p_e1l, be1, nullptr, p_arh, p_arl, 0, 2 * HRt, Dm);

    // --- Branch A (origin stream): shared expert path -> out ---
    wsplit_ilv_k<<<dim3((Dm * HSh + 255) / 256, 1), 256>>>(
        Ws1, p_w1h, p_w1l, Dm, HSh);
    fgemm<0, true><<<dim3(2 * HSh / 64, NTOK / 128), 256, GSMEM>>>(
        p_xh, p_xl, p_w1h, p_w1l, bs1, nullptr, p_ash, p_asl, NTOK, 2 * HSh, Dm);
    split_k<<<(HSh * Dm / 4 + 255) / 256, 256>>>(
        (const float4*)Ws2, (uint2*)p_w2h, (uint2*)p_w2l, HSh * Dm / 4);
    fgemm<0, false><<<dim3(Dm / 64, NTOK / 128), 256, GSMEM>>>(
        p_ash, p_asl, p_w2h, p_w2l, bs2, out, nullptr, nullptr, NTOK, Dm, HSh);

    // join: routed GEMM2 needs out (A) + g_ar/We2 (B)
    cudaEventRecord(evJ, sB);
    cudaStreamWaitEvent(0, evJ, 0);
    fgemm<2, false><<<dim3(Dm / 64, NTOK / 128, NEXP), 256, GSMEM>>>(
        p_arh, p_arl, p_e2h, p_e2l, be2, out, nullptr, nullptr, 0, Dm, HRt);
}

// round 11
// speedup vs baseline: 1.8685x; 1.0225x over previous
#include <cuda_runtime.h>
#include <cuda_bf16.h>
#include <math.h>
#include <stdint.h>

// ---------------- problem constants ----------------
static constexpr int NTOK = 2048;
static constexpr int Dm   = 1024;
static constexpr int NEXP = 12;
static constexpr int HSh  = 2048;   // shared hidden
static constexpr int HRt  = 3072;   // routed hidden
static constexpr float TAU = 1.5f;
static constexpr int NGRP = 3, EPG = NEXP / NGRP;   // expert pipeline groups

// ---------------- device scratch ----------------
__device__ int   g_cnt[NEXP];
__device__ int   g_off[NEXP];
__device__ int   g_bucket[NEXP * NTOK];
__device__ float g_bw[NEXP * NTOK];

__device__ __nv_bfloat16 g_xh[(size_t)NTOK * Dm],  g_xl[(size_t)NTOK * Dm];
__device__ __nv_bfloat16 g_ash[(size_t)NTOK * HSh], g_asl[(size_t)NTOK * HSh];
__device__ __nv_bfloat16 g_arh[(size_t)2 * NTOK * HRt], g_arl[(size_t)2 * NTOK * HRt];
// converted weights, SAME [K, N] layout as source (W1: a/g column-interleaved)
__device__ __nv_bfloat16 g_w1h[(size_t)Dm * 2 * HSh], g_w1l[(size_t)Dm * 2 * HSh];
__device__ __nv_bfloat16 g_w2h[(size_t)HSh * Dm],     g_w2l[(size_t)HSh * Dm];
__device__ __nv_bfloat16 g_e1h[(size_t)NEXP * Dm * 2 * HRt], g_e1l[(size_t)NEXP * Dm * 2 * HRt];
__device__ __nv_bfloat16 g_e2h[(size_t)NEXP * HRt * Dm],     g_e2l[(size_t)NEXP * HRt * Dm];

// ---------------- helpers ----------------
__device__ __forceinline__ uint32_t smem_u32(const void* p) {
    uint32_t a;
    asm("{ .reg .u64 t; cvta.to.shared.u64 t, %1; cvt.u32.u64 %0, t; }" : "=r"(a) : "l"(p));
    return a;
}
__device__ __forceinline__ uint32_t swzA(uint32_t b) { return b ^ ((b >> 3) & 0x70); }
// B tile: [64 k-rows][64 n-cols bf16] = 128B rows; 16B-granule xor swizzle
__device__ __forceinline__ uint32_t bofs(int k, int nb) {
    return (uint32_t)(k * 128 + (((nb >> 4) ^ (k & 7)) << 4) + (nb & 15));
}

__device__ __forceinline__ void cp16(uint32_t dst, const void* src, int sz) {
    asm volatile("cp.async.cg.shared.global [%0], [%1], 16, %2;"
                 :: "r"(dst), "l"(src), "r"(sz));
}
#define CP_COMMIT() asm volatile("cp.async.commit_group;" ::: "memory")

__device__ __forceinline__ void ldsm4(uint32_t* r, uint32_t addr) {
    asm volatile("ldmatrix.sync.aligned.m8n8.x4.shared.b16 {%0,%1,%2,%3}, [%4];"
                 : "=r"(r[0]), "=r"(r[1]), "=r"(r[2]), "=r"(r[3]) : "r"(addr));
}
__device__ __forceinline__ void ldsm4t(uint32_t* r, uint32_t addr) {
    asm volatile("ldmatrix.sync.aligned.m8n8.x4.trans.shared.b16 {%0,%1,%2,%3}, [%4];"
                 : "=r"(r[0]), "=r"(r[1]), "=r"(r[2]), "=r"(r[3]) : "r"(addr));
}
__device__ __forceinline__ void mma16816(float* c, const uint32_t* a, const uint32_t* b) {
    asm volatile(
        "mma.sync.aligned.m16n8k16.row.col.f32.bf16.bf16.f32 "
        "{%0,%1,%2,%3}, {%4,%5,%6,%7}, {%8,%9}, {%0,%1,%2,%3};"
        : "+f"(c[0]), "+f"(c[1]), "+f"(c[2]), "+f"(c[3])
        : "r"(a[0]), "r"(a[1]), "r"(a[2]), "r"(a[3]), "r"(b[0]), "r"(b[1]));
}
__device__ __forceinline__ void split_bf16(float v, __nv_bfloat16& h, __nv_bfloat16& l) {
    h = __float2bfloat16(v);
    l = __float2bfloat16(v - __bfloat162float(h));
}
__device__ __forceinline__ uint32_t pack2(__nv_bfloat16 a, __nv_bfloat16 b) {
    return (uint32_t)__bfloat16_as_ushort(a) | ((uint32_t)__bfloat16_as_ushort(b) << 16);
}
__device__ __forceinline__ float gelu_exact(float g) {
    return 0.5f * g * (1.0f + erff(g * 0.70710678118654752f));
}

// ---------------- tiny kernels ----------------
__global__ void zero_k() { if (threadIdx.x < NEXP) g_cnt[threadIdx.x] = 0; }

__global__ void prefix_k() {
    if (threadIdx.x == 0) {
        int s = 0;
        for (int e = 0; e < NEXP; e++) { g_off[e] = s; s += g_cnt[e]; }
    }
}

__global__ void router_k(const float* __restrict__ x,
                         const float* __restrict__ Wr,
                         const float* __restrict__ br) {
    int n = blockIdx.x, tid = threadIdx.x;            // 128 threads
    __shared__ float red[128 * NEXP];
    __shared__ float lg[NEXP];
    float part[NEXP];
#pragma unroll
    for (int e = 0; e < NEXP; e++) part[e] = 0.f;
    const float* xr = x + (size_t)n * Dm;
    for (int d = tid; d < Dm; d += 128) {
        float xv = xr[d];
        const float* wr = Wr + (size_t)d * NEXP;
#pragma unroll
        for (int e = 0; e < NEXP; e++) part[e] += xv * wr[e];
    }
#pragma unroll
    for (int e = 0; e < NEXP; e++) red[tid * NEXP + e] = part[e];
    __syncthreads();
    if (tid < NEXP) {
        float s = 0.f;
        for (int i = 0; i < 128; i++) s += red[i * NEXP + tid];
        lg[tid] = (s + br[tid]) / TAU;
    }
    __syncthreads();
    if (tid == 0) {
        int i0 = 0; float v0 = lg[0];
#pragma unroll
        for (int e = 1; e < NEXP; e++) if (lg[e] > v0) { v0 = lg[e]; i0 = e; }
        int i1 = -1; float v1 = -3.4e38f;
#pragma unroll
        for (int e = 0; e < NEXP; e++) if (e != i0 && lg[e] > v1) { v1 = lg[e]; i1 = e; }
        float e1 = __expf(v1 - v0);
        float inv = 1.f / (1.f + e1);
        int s0 = atomicAdd(&g_cnt[i0], 1);
        g_bucket[i0 * NTOK + s0] = n;  g_bw[i0 * NTOK + s0] = inv;
        int s1 = atomicAdd(&g_cnt[i1], 1);
        g_bucket[i1 * NTOK + s1] = n;  g_bw[i1 * NTOK + s1] = e1 * inv;
    }
}

// vectorized split fp32 -> bf16 hi/lo (layout-preserving, n multiple of 4)
__global__ void split_k(const float4* __restrict__ s, uint2* __restrict__ dh,
                        uint2* __restrict__ dl, int n4) {
    int i = blockIdx.x * 256 + threadIdx.x;
    if (i >= n4) return;
    float4 v = s[i];
    __nv_bfloat16 h[4], l[4];
    split_bf16(v.x, h[0], l[0]); split_bf16(v.y, h[1], l[1]);
    split_bf16(v.z, h[2], l[2]); split_bf16(v.w, h[3], l[3]);
    dh[i] = make_uint2(pack2(h[0], h[1]), pack2(h[2], h[3]));
    dl[i] = make_uint2(pack2(l[0], l[1]), pack2(l[2], l[3]));
}

// W1 conversion: fp32 [K, 2H] -> bf16 hi/lo [K, 2H] with a/g column interleave
__global__ void wsplit_ilv_k(const float* __restrict__ W, __nv_bfloat16* __restrict__ oh,
                             __nv_bfloat16* __restrict__ ol, int K, int H) {
    int i = blockIdx.x * 256 + threadIdx.x;
    if (i >= K * H) return;
    int k = i / H, c = i - k * H;
    size_t zo = (size_t)blockIdx.y * K * 2 * H;
    const float* wr = W + zo + (size_t)k * 2 * H;
    float a = wr[c], g = wr[H + c];
    __nv_bfloat16 ah, al, gh, gl;
    split_bf16(a, ah, al); split_bf16(g, gh, gl);
    size_t o = zo + (size_t)k * 2 * H + 2 * c;
    *(uint32_t*)(oh + o) = pack2(ah, gh);
    *(uint32_t*)(ol + o) = pack2(al, gl);
}

// ---------------- HMMA bf16x3 GEMM ----------------
// CTA 128M x 64N, 256 thr, 8 warps (4M x 2N), warp tile 32x32, 2 CTAs/SM.
// A: bf16 hi/lo [M,K] (swzA, ldsm4). B: bf16 hi/lo [K,N] (bofs, ldsm4t).
// 2-stage cp.async. GEGLU: interleaved a/g cols, epilogue writes bf16 hi/lo.
// MODE 0 plain; MODE 1 A via bucket (expert = ebase+blockIdx.z), out row off[e]+m;
// MODE 2 A rows off[e]+m, atomicAdd(C[token], w*(acc+bias)).
static constexpr int AT_B  = 16384;                 // A tile 128x64x2B
static constexpr int BT_B  = 8192;                  // B tile 64x64x2B
static constexpr int STG_B = 2 * AT_B + 2 * BT_B;   // 49152
static constexpr int GSMEM = 2 * STG_B;             // 98304

template <int MODE, bool GEGLU>
__global__ void __launch_bounds__(256, 2)
fgemm(const __nv_bfloat16* __restrict__ Ah, const __nv_bfloat16* __restrict__ Al,
      const __nv_bfloat16* __restrict__ Bh, const __nv_bfloat16* __restrict__ Bl,
      const float* __restrict__ bias, float* __restrict__ C,
      __nv_bfloat16* __restrict__ OH, __nv_bfloat16* __restrict__ OL,
      int M, int N, int K, int ebase) {
    extern __shared__ char sm[];
    __shared__ int   sb_tok[128];
    __shared__ float sb_w[128];

    const int tid = threadIdx.x, wid = tid >> 5, lane = tid & 31;
    const int wm = wid & 3, wn = wid >> 2;
    const int row0 = blockIdx.y * 128, col0 = blockIdx.x * 64;

    int e = 0, Me = M, offE = 0;
    if constexpr (MODE != 0) {
        e = ebase + blockIdx.z;
        Me = g_cnt[e];
        if (row0 >= Me) return;
        offE = g_off[e];
        Bh += (size_t)e * K * N;
        Bl += (size_t)e * K * N;
        bias += (size_t)e * N;
        if (tid < 128) {
            int r = row0 + tid;
            sb_tok[tid] = (r < Me) ? g_bucket[e * NTOK + r] : 0;
            sb_w[tid]   = (r < Me) ? g_bw[e * NTOK + r] : 0.f;
        }
        __syncthreads();
    }

    const int nch = K >> 6;
    const uint32_t smb = smem_u32(sm);

    auto issue_chunk = [&](int ck) {
        const int k0 = ck << 6;
        const uint32_t base = smb + (ck & 1) * STG_B;
#pragma unroll
        for (int s = tid; s < 2048; s += 256) {
            int t = s >> 10, slot = s & 1023;
            int r = slot >> 3, cc = slot & 7;
            uint32_t dst = base + t * AT_B + swzA((uint32_t)(r * 128 + cc * 16));
            const __nv_bfloat16* Ab = (t == 0) ? Ah : Al;
            size_t ro = 0; int sz = 16;
            if constexpr (MODE == 1) {
                if (row0 + r < Me) ro = (size_t)sb_tok[r] * K; else sz = 0;
            } else if constexpr (MODE == 2) {
                if (row0 + r < Me) ro = (size_t)(offE + row0 + r) * K; else sz = 0;
            } else {
                ro = (size_t)(row0 + r) * K;
            }
            cp16(dst, Ab + ro + k0 + cc * 8, sz);
        }
#pragma unroll
        for (int s = tid; s < 1024; s += 256) {
            int t = s >> 9, slot = s & 511;
            int k = slot >> 3, j16 = slot & 7;
            uint32_t dst = base + 2 * AT_B + t * BT_B + bofs(k, j16 * 16);
            const __nv_bfloat16* Bb = (t == 0) ? Bh : Bl;
            cp16(dst, Bb + (size_t)(k0 + k) * N + col0 + j16 * 8, 16);
        }
        CP_COMMIT();
    };

    float acc[2][4][4];
#pragma unroll
    for (int i = 0; i < 2; i++)
#pragma unroll
        for (int j = 0; j < 4; j++)
#pragma unroll
            for (int k = 0; k < 4; k++) acc[i][j][k] = 0.f;

    issue_chunk(0);
    for (int ck = 0; ck < nch; ck++) {
        if (ck + 1 < nch) {
            issue_chunk(ck + 1);
            asm volatile("cp.async.wait_group 1;" ::: "memory");
        } else {
            asm volatile("cp.async.wait_group 0;" ::: "memory");
        }
        __syncthreads();

        const uint32_t base = smb + (ck & 1) * STG_B;
        const uint32_t tAh = base, tAl = base + AT_B;
        const uint32_t tBh = base + 2 * AT_B, tBl = tBh + BT_B;

#pragma unroll
        for (int ks = 0; ks < 4; ks++) {
            uint32_t ahf[2][4], alf[2][4];
#pragma unroll
            for (int mt = 0; mt < 2; mt++) {
                int rrow = wm * 32 + mt * 16 + (lane & 15);
                uint32_t byte = swzA((uint32_t)(rrow * 128 + ks * 32 + (lane >> 4) * 16));
                ldsm4(ahf[mt], tAh + byte);
                ldsm4(alf[mt], tAl + byte);
            }
            const int sub = lane >> 3, i8 = lane & 7;
            const int kk = ks * 16 + (sub & 1) * 8 + i8;
            uint32_t bhf[4][2], blf[4][2];
#pragma unroll
            for (int g = 0; g < 2; g++) {
                int nn = wn * 32 + g * 16 + (sub >> 1) * 8;
                uint32_t byte = bofs(kk, nn * 2);
                uint32_t r4[4];
                ldsm4t(r4, tBh + byte);
                bhf[2 * g][0] = r4[0]; bhf[2 * g][1] = r4[1];
                bhf[2 * g + 1][0] = r4[2]; bhf[2 * g + 1][1] = r4[3];
                ldsm4t(r4, tBl + byte);
                blf[2 * g][0] = r4[0]; blf[2 * g][1] = r4[1];
                blf[2 * g + 1][0] = r4[2]; blf[2 * g + 1][1] = r4[3];
            }
#pragma unroll
            for (int mt = 0; mt < 2; mt++)
#pragma unroll
                for (int nf = 0; nf < 4; nf++) {
                    mma16816(acc[mt][nf], ahf[mt], bhf[nf]);
                    mma16816(acc[mt][nf], ahf[mt], blf[nf]);
                    mma16816(acc[mt][nf], alf[mt], bhf[nf]);
                }
        }
        __syncthreads();
    }

    // ---------------- epilogue ----------------
    const int Hout = N >> 1;
#pragma unroll
    for (int mt = 0; mt < 2; mt++) {
#pragma unroll
        for (int half = 0; half < 2; half++) {
            int ml = wm * 32 + mt * 16 + (lane >> 2) + half * 8;
            if constexpr (MODE != 0) { if (row0 + ml >= Me) continue; }
#pragma unroll
            for (int nf = 0; nf < 4; nf++) {
                int colb = col0 + wn * 32 + nf * 8 + (lane & 3) * 2;
                if constexpr (GEGLU) {
                    int c = colb >> 1;
                    float a = acc[mt][nf][half * 2 + 0] + __ldg(bias + c);
                    float g = acc[mt][nf][half * 2 + 1] + __ldg(bias + Hout + c);
                    float v = a * gelu_exact(g);
                    __nv_bfloat16 vh, vl; split_bf16(v, vh, vl);
                    size_t rr = (MODE != 0) ? (size_t)(offE + row0 + ml)
                                            : (size_t)(row0 + ml);
                    OH[rr * Hout + c] = vh;
                    OL[rr * Hout + c] = vl;
                } else {
                    float v0 = acc[mt][nf][half * 2 + 0] + __ldg(bias + colb + 0);
                    float v1 = acc[mt][nf][half * 2 + 1] + __ldg(bias + colb + 1);
                    if constexpr (MODE == 2) {
                        int tok = sb_tok[ml];
                        float w = sb_w[ml];
                        float* op = C + (size_t)tok * N + colb;
                        atomicAdd(op + 0, w * v0);
                        atomicAdd(op + 1, w * v1);
                    } else {
                        float2* cp = (float2*)(C + (size_t)(row0 + ml) * N + colb);
                        *cp = make_float2(v0, v1);
                    }
                }
            }
        }
    }
}

// ---------------- launch ----------------
extern "C" void kernel_launch(void* const* d_in, const int* in_sizes, int n_in,
                              void* d_out, int out_size) {
    const float* x   = (const float*)d_in[0];
    const float* Ws1 = (const float*)d_in[1];
    const float* bs1 = (const float*)d_in[2];
    const float* Ws2 = (const float*)d_in[3];
    const float* bs2 = (const float*)d_in[4];
    const float* We1 = (const float*)d_in[5];
    const float* be1 = (const float*)d_in[6];
    const float* We2 = (const float*)d_in[7];
    const float* be2 = (const float*)d_in[8];
    const float* Wr  = (const float*)d_in[9];
    const float* br  = (const float*)d_in[10];
    float* out = (float*)d_out;

    cudaFuncSetAttribute(fgemm<0, true>,  cudaFuncAttributeMaxDynamicSharedMemorySize, GSMEM);
    cudaFuncSetAttribute(fgemm<0, false>, cudaFuncAttributeMaxDynamicSharedMemorySize, GSMEM);
    cudaFuncSetAttribute(fgemm<1, true>,  cudaFuncAttributeMaxDynamicSharedMemorySize, GSMEM);
    cudaFuncSetAttribute(fgemm<2, false>, cudaFuncAttributeMaxDynamicSharedMemorySize, GSMEM);

    __nv_bfloat16 *p_xh, *p_xl, *p_ash, *p_asl, *p_arh, *p_arl;
    __nv_bfloat16 *p_w1h, *p_w1l, *p_w2h, *p_w2l, *p_e1h, *p_e1l, *p_e2h, *p_e2l;
    cudaGetSymbolAddress((void**)&p_xh, g_xh);   cudaGetSymbolAddress((void**)&p_xl, g_xl);
    cudaGetSymbolAddress((void**)&p_ash, g_ash); cudaGetSymbolAddress((void**)&p_asl, g_asl);
    cudaGetSymbolAddress((void**)&p_arh, g_arh); cudaGetSymbolAddress((void**)&p_arl, g_arl);
    cudaGetSymbolAddress((void**)&p_w1h, g_w1h); cudaGetSymbolAddress((void**)&p_w1l, g_w1l);
    cudaGetSymbolAddress((void**)&p_w2h, g_w2h); cudaGetSymbolAddress((void**)&p_w2l, g_w2l);
    cudaGetSymbolAddress((void**)&p_e1h, g_e1h); cudaGetSymbolAddress((void**)&p_e1l, g_e1l);
    cudaGetSymbolAddress((void**)&p_e2h, g_e2h); cudaGetSymbolAddress((void**)&p_e2l, g_e2l);

    // one-time host resources (streams/events only; no device alloc)
    static cudaStream_t sB = nullptr, sC = nullptr;
    static cudaEvent_t  evF = nullptr, evJ = nullptr, evG[NGRP] = {};
    if (!sB) {
        cudaStreamCreateWithFlags(&sB, cudaStreamNonBlocking);
        cudaStreamCreateWithFlags(&sC, cudaStreamNonBlocking);
        cudaEventCreateWithFlags(&evF, cudaEventDisableTiming);
        cudaEventCreateWithFlags(&evJ, cudaEventDisableTiming);
        for (int g = 0; g < NGRP; g++)
            cudaEventCreateWithFlags(&evG[g], cudaEventDisableTiming);
    }

    // --- common prefix on origin stream ---
    split_k<<<(NTOK * Dm / 4 + 255) / 256, 256>>>(
        (const float4*)x, (uint2*)p_xh, (uint2*)p_xl, NTOK * Dm / 4);
    zero_k<<<1, 32>>>();
    cudaEventRecord(evF, 0);
    cudaStreamWaitEvent(sB, evF, 0);
    cudaStreamWaitEvent(sC, evF, 0);

    // --- stream B: We1 conversion in expert groups (feeds stream C) ---
    const size_t e1slab = (size_t)Dm * 2 * HRt;     // elems per expert
    for (int g = 0; g < NGRP; g++) {
        wsplit_ilv_k<<<dim3((Dm * HRt + 255) / 256, EPG), 256, 0, sB>>>(
            We1 + (size_t)g * EPG * e1slab,
            p_e1h + (size_t)g * EPG * e1slab,
            p_e1l + (size_t)g * EPG * e1slab, Dm, HRt);
        cudaEventRecord(evG[g], sB);
    }

    // --- stream C: routing, then routed GEMM1 per group (pipelined vs conv) ---
    router_k<<<NTOK, 128, 0, sC>>>(x, Wr, br);
    prefix_k<<<1, 1, 0, sC>>>();
    for (int g = 0; g < NGRP; g++) {
        cudaStreamWaitEvent(sC, evG[g], 0);
        fgemm<1, true><<<dim3(2 * HRt / 64, NTOK / 128, EPG), 256, GSMEM, sC>>>(
            p_xh, p_xl, p_e1h, p_e1l, be1, nullptr, p_arh, p_arl,
            0, 2 * HRt, Dm, g * EPG);
    }
    cudaEventRecord(evJ, sC);

    // --- origin stream (branch A): shared expert path + We2 conversion ---
    wsplit_ilv_k<<<dim3((Dm * HSh + 255) / 256, 1), 256>>>(
        Ws1, p_w1h, p_w1l, Dm, HSh);
    fgemm<0, true><<<dim3(2 * HSh / 64, NTOK / 128), 256, GSMEM>>>(
        p_xh, p_xl, p_w1h, p_w1l, bs1, nullptr, p_ash, p_asl, NTOK, 2 * HSh, Dm, 0);
    split_k<<<(HSh * Dm / 4 + 255) / 256, 256>>>(
        (const float4*)Ws2, (uint2*)p_w2h, (uint2*)p_w2l, HSh * Dm / 4);
    fgemm<0, false><<<dim3(Dm / 64, NTOK / 128), 256, GSMEM>>>(
        p_ash, p_asl, p_w2h, p_w2l, bs2, out, nullptr, nullptr, NTOK, Dm, HSh, 0);
    split_k<<<(NEXP * HRt * Dm / 4 + 255) / 256, 256>>>(
        (const float4*)We2, (uint2*)p_e2h, (uint2*)p_e2l, NEXP * HRt * Dm / 4);

    // --- join: routed GEMM2 needs out + We2 (origin) and g_ar (stream C) ---
    cudaStreamWaitEvent(0, evJ, 0);
    fgemm<2, false><<<dim3(Dm / 64, NTOK / 128, NEXP), 256, GSMEM>>>(
        p_arh, p_arl, p_e2h, p_e2l, be2, out, nullptr, nullptr, 0, Dm, HRt, 0);
}